// round 13
// baseline (speedup 1.0000x reference)
#include <cuda_runtime.h>
#include <cstdint>
#include <math.h>

#define BB 2
#define SS 1024
#define DD 1024
#define HH 16
#define HD 64
#define LL 4
#define VV 32000
#define NROW (BB * SS)      // 2048
#define NT_OUT (VV / 128)   // 250
#define NT_D   (DD / 128)   // 8
#define MT_A   (NROW / 128) // 16
#define KC_D   (DD / 32)    // 32

// ---------------- scratch (static device globals; no allocs allowed) --------
__device__ float g_x[NROW * DD];
__device__ float g_q[NROW * DD];
__device__ float g_k[NROW * DD];
__device__ float g_v[NROW * DD];
__device__ float g_ctx[NROW * DD];
__device__ float g_attn[NROW * DD];
__device__ float g_afrag[MT_A * KC_D * 4096];                       // 8 MB
__device__ float g_wfrag[(size_t)NT_OUT * KC_D * 4096];             // 131 MB
__device__ float g_lwf[(size_t)LL * 4 * NT_D * KC_D * 4096];        // 64 MB

__device__ __forceinline__ float tf32r(float x) {
    float r; asm("cvt.rna.tf32.f32 %0, %1;" : "=f"(r) : "f"(x)); return r;
}

__device__ __forceinline__ void mma16n8k8(float* d, const float* a, float bx, float by) {
    asm volatile(
        "mma.sync.aligned.m16n8k8.row.col.f32.tf32.tf32.f32 "
        "{%0,%1,%2,%3}, {%4,%5,%6,%7}, {%8,%9}, {%0,%1,%2,%3};"
        : "+f"(d[0]), "+f"(d[1]), "+f"(d[2]), "+f"(d[3])
        : "r"(__float_as_uint(a[0])), "r"(__float_as_uint(a[1])),
          "r"(__float_as_uint(a[2])), "r"(__float_as_uint(a[3])),
          "r"(__float_as_uint(bx)), "r"(__float_as_uint(by)));
}

__device__ __forceinline__ uint32_t smem_u32(const void* p) {
    uint32_t a;
    asm("{ .reg .u64 t; cvta.to.shared.u64 t, %1; cvt.u32.u64 %0, t; }" : "=r"(a) : "l"(p));
    return a;
}
__device__ __forceinline__ void cpasync16(uint32_t dst, const void* src) {
    asm volatile("cp.async.cg.shared.global [%0], [%1], 16;" :: "r"(dst), "l"(src));
}
#define CP_COMMIT() asm volatile("cp.async.commit_group;" ::: "memory")
#define CP_WAIT(n)  asm volatile("cp.async.wait_group %0;" :: "n"(n) : "memory")

// scatter one tf32-rounded float4 of row `row`, k-chunk kc, quad c4 into afrag
__device__ __forceinline__ void scatterA(float* __restrict__ afrag, int row, int kc,
                                         int c4, const float* vv)
{
    int mt = row >> 7, r127 = row & 127;
    int mi = r127 >> 4, m16 = r127 & 15;
    int ga = m16 & 7, rA = m16 >> 3;
    int ki = c4 >> 1, khi = c4 & 1;
    float* dst = afrag + ((size_t)mt * KC_D + kc) * 4096;
    int base = ((mi * 4 + ki) * 32) * 4 + (rA + 2 * khi);
#pragma unroll
    for (int e = 0; e < 4; e++)
        dst[base + ((ga * 4 + e) ^ ki) * 4] = vv[e];
}

// =================== prelayout kernels ======================================
__global__ void __launch_bounds__(256)
prelayout_A(const float* __restrict__ A, float* __restrict__ out, int K)
{
    const int kc = blockIdx.x;
    const int mt = blockIdx.y;
    const int t  = threadIdx.x;
    float* dst = out + ((size_t)mt * gridDim.x + kc) * 4096;
#pragma unroll
    for (int i = 0; i < 4; i++) {
        int idx = t + i * 256;
        int row = idx >> 3, c4 = idx & 7;
        int mi = row >> 4, m16 = row & 15;
        int ga = m16 & 7, rA = m16 >> 3;
        int ki = c4 >> 1, khi = c4 & 1;
        int base = ((mi * 4 + ki) * 32) * 4 + (rA + 2 * khi);
        float4 v = *(const float4*)(A + (size_t)(mt * 128 + row) * K + kc * 32 + c4 * 4);
        float vv[4] = {tf32r(v.x), tf32r(v.y), tf32r(v.z), tf32r(v.w)};
#pragma unroll
        for (int e = 0; e < 4; e++) {
            int lp = (ga * 4 + e) ^ ki;
            dst[base + lp * 4] = vv[e];
        }
    }
}

__global__ void __launch_bounds__(256)
prelayout_W(const float* __restrict__ W, float* __restrict__ out, int N)
{
    const int kc = blockIdx.x;
    const int nt = blockIdx.y;
    const int t  = threadIdx.x;
    float* dst = out + ((size_t)nt * gridDim.x + kc) * 4096;
#pragma unroll
    for (int i = 0; i < 4; i++) {
        int idx = t + i * 256;
        int rowk = idx >> 5, c4 = idx & 31;
        int n0 = c4 * 4;
        int ki = rowk >> 3, kk = rowk & 7;
        int tgb = kk & 3, hi = kk >> 2;
        int ni = n0 >> 3, g0 = n0 & 7;
        int swz = ((ni & 3) << 3) ^ (((ni >> 2) & 3) << 1);
        int ln0 = g0 * 4 + tgb;
        int base = ((ni * 4 + ki) * 32) * 2 + hi;
        float4 v = *(const float4*)(W + (size_t)(kc * 32 + rowk) * N + nt * 128 + n0);
        float vv[4] = {tf32r(v.x), tf32r(v.y), tf32r(v.z), tf32r(v.w)};
#pragma unroll
        for (int e = 0; e < 4; e++) {
            int lp = (ln0 + 4 * e) ^ swz;
            dst[base + lp * 2] = vv[e];
        }
    }
}

// ============== GEMM on prelaid operands, cp.async 3-stage ring =============
#define PSTAGES 3
#define STAGE_FLOATS 8192
#define GEMM_PRE_SMEM_BYTES (PSTAGES * STAGE_FLOATS * 4)   // 96 KB

__device__ __forceinline__ void gemm_pre_core(
    const float* __restrict__ aSrc, const float* __restrict__ bSrc,
    const float* __restrict__ bias, float* __restrict__ C,
    int N, int nkc, int mt, int nt, float* sm)
{
    const int t    = threadIdx.x;
    const int lane = t & 31;
    const int wid  = t >> 5;
    const int g    = lane >> 2;
    const int tg   = lane & 3;
    const int wm   = (wid & 1) * 64;
    const int wn   = (wid >> 1) * 32;
    const uint32_t smb = smem_u32(sm);

    float acc[4][4][4];
#pragma unroll
    for (int mf = 0; mf < 4; mf++)
#pragma unroll
        for (int nf = 0; nf < 4; nf++)
#pragma unroll
            for (int r = 0; r < 4; r++) acc[mf][nf][r] = 0.0f;

    auto issue = [&](int c) {
        uint32_t dstA = smb + (uint32_t)((c % PSTAGES) * STAGE_FLOATS) * 4u;
        uint32_t dstB = dstA + 4096u * 4u;
        const float* sa = aSrc + (size_t)c * 4096;
        const float* sb = bSrc + (size_t)c * 4096;
#pragma unroll
        for (int i = 0; i < 4; i++) {
            int o4 = (t + i * 256) * 4;
            cpasync16(dstA + (uint32_t)o4 * 4u, sa + o4);
            cpasync16(dstB + (uint32_t)o4 * 4u, sb + o4);
        }
        CP_COMMIT();
    };

    issue(0);
    issue(1);

    int bswz[4];
#pragma unroll
    for (int nf = 0; nf < 4; nf++) {
        int ni = (wid >> 1) * 4 + nf;
        bswz[nf] = lane ^ ((ni & 3) << 3) ^ (((ni >> 2) & 3) << 1);
    }

    for (int kt = 0; kt < nkc; kt++) {
        if (kt + 1 < nkc) { CP_WAIT(1); } else { CP_WAIT(0); }
        __syncthreads();
        if (kt + 2 < nkc) issue(kt + 2);

        const float* asb = sm + (kt % PSTAGES) * STAGE_FLOATS;
        const float* bsb = asb + 4096;
#pragma unroll
        for (int ki = 0; ki < 4; ki++) {
            float4 afv[4];
            float2 bfv[4];
#pragma unroll
            for (int mf = 0; mf < 4; mf++) {
                int mi = (wid & 1) * 4 + mf;
                afv[mf] = *(const float4*)(asb + ((mi * 4 + ki) * 32 + (lane ^ ki)) * 4);
            }
#pragma unroll
            for (int nf = 0; nf < 4; nf++) {
                int ni = (wid >> 1) * 4 + nf;
                bfv[nf] = *(const float2*)(bsb + ((ni * 4 + ki) * 32 + bswz[nf]) * 2);
            }
#pragma unroll
            for (int mf = 0; mf < 4; mf++)
#pragma unroll
                for (int nf = 0; nf < 4; nf++)
                    mma16n8k8(acc[mf][nf], (const float*)&afv[mf], bfv[nf].x, bfv[nf].y);
        }
    }

#pragma unroll
    for (int mf = 0; mf < 4; mf++) {
        const int r0 = mt * 128 + wm + mf * 16 + g;
        const int r1 = r0 + 8;
#pragma unroll
        for (int nf = 0; nf < 4; nf++) {
            const int col = nt * 128 + wn + nf * 8 + tg * 2;
            const float b0 = bias[col], b1 = bias[col + 1];
            float2 v0 = make_float2(acc[mf][nf][0] + b0, acc[mf][nf][1] + b1);
            float2 v1 = make_float2(acc[mf][nf][2] + b0, acc[mf][nf][3] + b1);
            *(float2*)(C + (size_t)r0 * N + col) = v0;
            *(float2*)(C + (size_t)r1 * N + col) = v1;
        }
    }
}

__global__ void __launch_bounds__(256, 2)
gemm_pre(const float* __restrict__ afrag, const float* __restrict__ wfrag,
         const float* __restrict__ bias, float* __restrict__ C,
         int N, int nkc)
{
    extern __shared__ float sm[];
    const int mt = blockIdx.x, nt = blockIdx.y;
    gemm_pre_core(afrag + (size_t)mt * nkc * 4096,
                  wfrag + (size_t)nt * nkc * 4096,
                  bias, C, N, nkc, mt, nt, sm);
}

__global__ void __launch_bounds__(256, 2)
gemm_pre_qkv(const float* __restrict__ afrag,
             const float* __restrict__ qwf, const float* __restrict__ kwf,
             const float* __restrict__ vwf,
             const float* __restrict__ qb, const float* __restrict__ kb,
             const float* __restrict__ vb,
             float* __restrict__ qo, float* __restrict__ ko, float* __restrict__ vo)
{
    extern __shared__ float sm[];
    const int mt = blockIdx.x, nt = blockIdx.y;
    const float* wf   = (blockIdx.z == 0) ? qwf : (blockIdx.z == 1) ? kwf : vwf;
    const float* bias = (blockIdx.z == 0) ? qb  : (blockIdx.z == 1) ? kb  : vb;
    float*       C    = (blockIdx.z == 0) ? qo  : (blockIdx.z == 1) ? ko  : vo;
    gemm_pre_core(afrag + (size_t)mt * KC_D * 4096,
                  wf    + (size_t)nt * KC_D * 4096,
                  bias, C, DD, KC_D, mt, nt, sm);
}

// -------- embedding + positional encoding; also emits fragment-major x -----
__global__ void __launch_bounds__(256)
embed_kernel(const int* __restrict__ tokens, const float* __restrict__ emb,
             float* __restrict__ x, float* __restrict__ afrag)
{
    int row = blockIdx.x;
    int pos = row & (SS - 1);
    int tok = tokens[row];
    const float* e = emb + (size_t)tok * DD;
    float* xr = x + (size_t)row * DD;
    const float c = -logf(10000.0f) / (float)DD;
    const int d0 = threadIdx.x * 4;
    float vv[4];
#pragma unroll
    for (int j = 0; j < 4; j++) {
        int d = d0 + j;
        int i = d >> 1;
        float ang = (float)pos * expf((float)(2 * i) * c);
        float pe = (d & 1) ? cosf(ang) : sinf(ang);
        vv[j] = e[d] + pe;
    }
    *(float4*)(xr + d0) = *(float4*)vv;
    float tv[4] = {tf32r(vv[0]), tf32r(vv[1]), tf32r(vv[2]), tf32r(vv[3])};
    scatterA(afrag, row, d0 >> 5, (d0 & 31) >> 2, tv);
}

// ============= tensor-core causal flash attention (tf32 mma) ================
// 256 threads = 8 warps; warp owns 16 query rows (one m16n8k8 row-block).
__global__ void __launch_bounds__(256)
attn_mma_kernel(const float* __restrict__ Q, const float* __restrict__ K,
                const float* __restrict__ V, float* __restrict__ O)
{
    __shared__ __align__(16) float Ks[32][68];
    __shared__ __align__(16) float Vs[32][72];
    __shared__ __align__(16) float Ps[8][16][36];

    const int b  = blockIdx.z;
    const int h  = blockIdx.y;
    const int qb = blockIdx.x * 128;
    const int tid = threadIdx.x;
    const int w    = tid >> 5;       // 0..7
    const int lane = tid & 31;
    const int g    = lane >> 2;
    const int tg   = lane & 3;
    const size_t base = (size_t)(b * SS) * DD + (size_t)h * HD;

    // Q as A-fragments (one 16-row block per warp), scaled + tf32-rounded
    float qf[8][4];
    {
        const int r0 = qb + w * 16 + g;
        const int r1 = r0 + 8;
#pragma unroll
        for (int k8 = 0; k8 < 8; k8++) {
            int k0 = k8 * 8;
            qf[k8][0] = tf32r(Q[base + (size_t)r0 * DD + k0 + tg]     * 0.125f);
            qf[k8][1] = tf32r(Q[base + (size_t)r1 * DD + k0 + tg]     * 0.125f);
            qf[k8][2] = tf32r(Q[base + (size_t)r0 * DD + k0 + tg + 4] * 0.125f);
            qf[k8][3] = tf32r(Q[base + (size_t)r1 * DD + k0 + tg + 4] * 0.125f);
        }
    }

    float oacc[8][4];
#pragma unroll
    for (int nf = 0; nf < 8; nf++)
#pragma unroll
        for (int r = 0; r < 4; r++) oacc[nf][r] = 0.0f;
    float m0 = -1e30f, m1 = -1e30f, l0 = 0.0f, l1 = 0.0f;

    const int qmax_w = qb + w * 16 + 15;
    const int kend = qb + 128;
    for (int kt = 0; kt < kend; kt += 32) {
        // cooperative K/V load: 512 float4 each over 256 threads
#pragma unroll
        for (int i = 0; i < 2; i++) {
            int idx4 = tid + i * 256;
            int r = idx4 >> 4;
            int c = (idx4 & 15) * 4;
            size_t ga = base + (size_t)(kt + r) * DD + c;
            float4 kv = *(const float4*)(K + ga);
            float4 vv = *(const float4*)(V + ga);
            Ks[r][c]   = tf32r(kv.x); Ks[r][c+1] = tf32r(kv.y);
            Ks[r][c+2] = tf32r(kv.z); Ks[r][c+3] = tf32r(kv.w);
            Vs[r][c]   = tf32r(vv.x); Vs[r][c+1] = tf32r(vv.y);
            Vs[r][c+2] = tf32r(vv.z); Vs[r][c+3] = tf32r(vv.w);
        }
        __syncthreads();

        if (kt <= qmax_w) {   // warp-uniform skip of fully-masked tiles
            // ---- S = Q.K^T ----
            float sacc[4][4];
#pragma unroll
            for (int nf = 0; nf < 4; nf++)
#pragma unroll
                for (int r = 0; r < 4; r++) sacc[nf][r] = 0.0f;
#pragma unroll
            for (int k8 = 0; k8 < 8; k8++) {
                float2 bf[4];
#pragma unroll
                for (int nf = 0; nf < 4; nf++) {
                    bf[nf].x = Ks[nf * 8 + g][k8 * 8 + tg];
                    bf[nf].y = Ks[nf * 8 + g][k8 * 8 + tg + 4];
                }
#pragma unroll
                for (int nf = 0; nf < 4; nf++)
                    mma16n8k8(sacc[nf], qf[k8], bf[nf].x, bf[nf].y);
            }

            // ---- mask + online softmax ----
            const int row0 = qb + w * 16 + g;
            const int row1 = row0 + 8;
#pragma unroll
            for (int nf = 0; nf < 4; nf++) {
#pragma unroll
                for (int e = 0; e < 2; e++) {
                    int key = kt + nf * 8 + tg * 2 + e;
                    if (key > row0) sacc[nf][e]     = -1e30f;
                    if (key > row1) sacc[nf][2 + e] = -1e30f;
                }
            }
            float t0 = -1e30f, t1 = -1e30f;
#pragma unroll
            for (int nf = 0; nf < 4; nf++) {
                t0 = fmaxf(t0, fmaxf(sacc[nf][0], sacc[nf][1]));
                t1 = fmaxf(t1, fmaxf(sacc[nf][2], sacc[nf][3]));
            }
            t0 = fmaxf(t0, __shfl_xor_sync(0xFFFFFFFFu, t0, 1));
            t0 = fmaxf(t0, __shfl_xor_sync(0xFFFFFFFFu, t0, 2));
            t1 = fmaxf(t1, __shfl_xor_sync(0xFFFFFFFFu, t1, 1));
            t1 = fmaxf(t1, __shfl_xor_sync(0xFFFFFFFFu, t1, 2));
            float nm0 = fmaxf(m0, t0);
            float nm1 = fmaxf(m1, t1);
            float c0 = __expf(m0 - nm0);
            float c1 = __expf(m1 - nm1);
            m0 = nm0; m1 = nm1;

            float ps0 = 0.0f, ps1 = 0.0f;
#pragma unroll
            for (int nf = 0; nf < 4; nf++) {
#pragma unroll
                for (int e = 0; e < 2; e++) {
                    float p0 = __expf(sacc[nf][e]     - nm0);
                    float p1 = __expf(sacc[nf][2 + e] - nm1);
                    sacc[nf][e]     = p0;
                    sacc[nf][2 + e] = p1;
                    ps0 += p0; ps1 += p1;
                }
            }
            ps0 += __shfl_xor_sync(0xFFFFFFFFu, ps0, 1);
            ps0 += __shfl_xor_sync(0xFFFFFFFFu, ps0, 2);
            ps1 += __shfl_xor_sync(0xFFFFFFFFu, ps1, 1);
            ps1 += __shfl_xor_sync(0xFFFFFFFFu, ps1, 2);
            l0 = l0 * c0 + ps0;
            l1 = l1 * c1 + ps1;

#pragma unroll
            for (int nf2 = 0; nf2 < 8; nf2++) {
                oacc[nf2][0] *= c0; oacc[nf2][1] *= c0;
                oacc[nf2][2] *= c1; oacc[nf2][3] *= c1;
            }
#pragma unroll
            for (int nf = 0; nf < 4; nf++) {
                float2 lo = make_float2(tf32r(sacc[nf][0]), tf32r(sacc[nf][1]));
                float2 hi = make_float2(tf32r(sacc[nf][2]), tf32r(sacc[nf][3]));
                *(float2*)&Ps[w][g][nf * 8 + tg * 2]     = lo;
                *(float2*)&Ps[w][g + 8][nf * 8 + tg * 2] = hi;
            }
            __syncwarp();

            // ---- O += P.V ----
#pragma unroll
            for (int kk = 0; kk < 4; kk++) {
                float af[4];
                af[0] = Ps[w][g][kk * 8 + tg];
                af[1] = Ps[w][g + 8][kk * 8 + tg];
                af[2] = Ps[w][g][kk * 8 + tg + 4];
                af[3] = Ps[w][g + 8][kk * 8 + tg + 4];
#pragma unroll
                for (int nf2 = 0; nf2 < 8; nf2++) {
                    float bx = Vs[kk * 8 + tg][nf2 * 8 + g];
                    float by = Vs[kk * 8 + tg + 4][nf2 * 8 + g];
                    mma16n8k8(oacc[nf2], af, bx, by);
                }
            }
        }
        __syncthreads();
    }

    // ---- epilogue ----
    {
        const int row0 = qb + w * 16 + g;
        const int row1 = row0 + 8;
        const float inv0 = 1.0f / l0;
        const float inv1 = 1.0f / l1;
#pragma unroll
        for (int nf2 = 0; nf2 < 8; nf2++) {
            const int col = nf2 * 8 + tg * 2;
            float2 v0 = make_float2(oacc[nf2][0] * inv0, oacc[nf2][1] * inv0);
            float2 v1 = make_float2(oacc[nf2][2] * inv1, oacc[nf2][3] * inv1);
            *(float2*)(O + base + (size_t)row0 * DD + col) = v0;
            *(float2*)(O + base + (size_t)row1 * DD + col) = v1;
        }
    }
}

// ------- residual add + layernorm; also emits fragment-major x -------------
__global__ void __launch_bounds__(256)
ln_res_kernel(float* __restrict__ x, const float* __restrict__ res,
              const float* __restrict__ g, const float* __restrict__ beta,
              float* __restrict__ afrag)
{
    __shared__ float red[256];
    const int row = blockIdx.x;
    const int tid = threadIdx.x;
    const int d0  = tid * 4;
    float* xr = x + (size_t)row * DD;
    const float* rr = res + (size_t)row * DD;

    float y[4];
    float s = 0.0f;
    {
        float4 xv = *(const float4*)(xr + d0);
        float4 rv = *(const float4*)(rr + d0);
        y[0] = xv.x + rv.x; y[1] = xv.y + rv.y;
        y[2] = xv.z + rv.z; y[3] = xv.w + rv.w;
        s = y[0] + y[1] + y[2] + y[3];
    }
    red[tid] = s; __syncthreads();
    for (int off = 128; off > 0; off >>= 1) {
        if (tid < off) red[tid] += red[tid + off];
        __syncthreads();
    }
    float mu = red[0] * (1.0f / (float)DD);
    __syncthreads();

    float vs = 0.0f;
#pragma unroll
    for (int i = 0; i < 4; i++) {
        float d2 = y[i] - mu;
        vs += d2 * d2;
    }
    red[tid] = vs; __syncthreads();
    for (int off = 128; off > 0; off >>= 1) {
        if (tid < off) red[tid] += red[tid + off];
        __syncthreads();
    }
    float var = red[0] * (1.0f / (float)DD);
    float inv = rsqrtf(var + 1e-5f);

    float out[4];
#pragma unroll
    for (int i = 0; i < 4; i++)
        out[i] = (y[i] - mu) * inv * g[d0 + i] + beta[d0 + i];
    *(float4*)(xr + d0) = *(float4*)out;
    float tv[4] = {tf32r(out[0]), tf32r(out[1]), tf32r(out[2]), tf32r(out[3])};
    scatterA(afrag, row, d0 >> 5, (d0 & 31) >> 2, tv);
}

// ---------------------------------------------------------------------------
extern "C" void kernel_launch(void* const* d_in, const int* in_sizes, int n_in,
                              void* d_out, int out_size)
{
    const int*   tokens = (const int*)  d_in[0];
    const float* emb    = (const float*)d_in[1];
    const float* qw     = (const float*)d_in[2];
    const float* qb     = (const float*)d_in[3];
    const float* kw     = (const float*)d_in[4];
    const float* kb     = (const float*)d_in[5];
    const float* vw     = (const float*)d_in[6];
    const float* vb     = (const float*)d_in[7];
    const float* ow     = (const float*)d_in[8];
    const float* ob     = (const float*)d_in[9];
    const float* ln_g   = (const float*)d_in[10];
    const float* ln_b   = (const float*)d_in[11];
    const float* out_w  = (const float*)d_in[12];
    const float* out_b  = (const float*)d_in[13];
    float* logits = (float*)d_out;

    float *x, *q, *k, *v, *ctx, *attn, *afrag, *wfrag, *lwf;
    cudaGetSymbolAddress((void**)&x,     g_x);
    cudaGetSymbolAddress((void**)&q,     g_q);
    cudaGetSymbolAddress((void**)&k,     g_k);
    cudaGetSymbolAddress((void**)&v,     g_v);
    cudaGetSymbolAddress((void**)&ctx,   g_ctx);
    cudaGetSymbolAddress((void**)&attn,  g_attn);
    cudaGetSymbolAddress((void**)&afrag, g_afrag);
    cudaGetSymbolAddress((void**)&wfrag, g_wfrag);
    cudaGetSymbolAddress((void**)&lwf,   g_lwf);

    cudaFuncSetAttribute(gemm_pre,     cudaFuncAttributeMaxDynamicSharedMemorySize, GEMM_PRE_SMEM_BYTES);
    cudaFuncSetAttribute(gemm_pre_qkv, cudaFuncAttributeMaxDynamicSharedMemorySize, GEMM_PRE_SMEM_BYTES);

    const size_t WMAT = (size_t)NT_D * KC_D * 4096;

    // one-time weight prelayouts
    {
        dim3 gw(KC_D, NT_OUT);
        prelayout_W<<<gw, 256>>>(out_w, wfrag, VV);
        dim3 gl(KC_D, NT_D);
        for (int l = 0; l < LL; l++) {
            size_t wo = (size_t)l * DD * DD;
            prelayout_W<<<gl, 256>>>(qw + wo, lwf + (size_t)(l * 4 + 0) * WMAT, DD);
            prelayout_W<<<gl, 256>>>(kw + wo, lwf + (size_t)(l * 4 + 1) * WMAT, DD);
            prelayout_W<<<gl, 256>>>(vw + wo, lwf + (size_t)(l * 4 + 2) * WMAT, DD);
            prelayout_W<<<gl, 256>>>(ow + wo, lwf + (size_t)(l * 4 + 3) * WMAT, DD);
        }
    }

    // embed writes x AND fragment-major afrag
    embed_kernel<<<NROW, 256>>>(tokens, emb, x, afrag);

    dim3 gpreA(KC_D, MT_A);               // (32, 16)
    dim3 gqkv(MT_A, NT_D, 3);             // (16, 8, 3)
    dim3 gproj(MT_A, NT_D);               // (16, 8)
    dim3 gattn(SS / 128, HH, BB);         // (8, 16, 2)

    for (int l = 0; l < LL; l++) {
        size_t bo = (size_t)l * DD;
        // afrag already holds fragment-major x (embed or previous ln)
        gemm_pre_qkv<<<gqkv, 256, GEMM_PRE_SMEM_BYTES>>>(
            afrag,
            lwf + (size_t)(l * 4 + 0) * WMAT,
            lwf + (size_t)(l * 4 + 1) * WMAT,
            lwf + (size_t)(l * 4 + 2) * WMAT,
            qb + bo, kb + bo, vb + bo, q, k, v);
        attn_mma_kernel<<<gattn, 256>>>(q, k, v, ctx);
        prelayout_A<<<gpreA, 256>>>(ctx, afrag, DD);
        gemm_pre<<<gproj, 256, GEMM_PRE_SMEM_BYTES>>>(
            afrag, lwf + (size_t)(l * 4 + 3) * WMAT, ob + bo, attn, DD, KC_D);
        ln_res_kernel<<<NROW, 256>>>(x, attn, ln_g + bo, ln_b + bo, afrag);
    }

    // final logits: afrag holds fragment-major x from last ln
    dim3 gout(MT_A, NT_OUT);              // (16, 250)
    gemm_pre<<<gout, 256, GEMM_PRE_SMEM_BYTES>>>(afrag, wfrag, out_b, logits, VV, KC_D);
}

// round 14
// speedup vs baseline: 1.0210x; 1.0210x over previous
#include <cuda_runtime.h>
#include <cstdint>
#include <math.h>

#define BB 2
#define SS 1024
#define DD 1024
#define HH 16
#define HD 64
#define LL 4
#define VV 32000
#define NROW (BB * SS)      // 2048
#define NT_OUT (VV / 128)   // 250
#define NT_D   (DD / 128)   // 8
#define MT_A   (NROW / 128) // 16
#define KC_D   (DD / 32)    // 32

// ---------------- scratch (static device globals; no allocs allowed) --------
__device__ float g_x[NROW * DD];
__device__ float g_q[NROW * DD];
__device__ float g_k[NROW * DD];
__device__ float g_v[NROW * DD];
__device__ float g_ctx[NROW * DD];
__device__ float g_attn[NROW * DD];
__device__ float g_afrag[MT_A * KC_D * 4096];                       // 8 MB
__device__ float g_wfrag[(size_t)NT_OUT * KC_D * 4096];             // 131 MB
__device__ float g_lwf[(size_t)LL * 4 * NT_D * KC_D * 4096];        // 64 MB

__device__ __forceinline__ float tf32r(float x) {
    float r; asm("cvt.rna.tf32.f32 %0, %1;" : "=f"(r) : "f"(x)); return r;
}

__device__ __forceinline__ void mma16n8k8(float* d, const float* a, float bx, float by) {
    asm volatile(
        "mma.sync.aligned.m16n8k8.row.col.f32.tf32.tf32.f32 "
        "{%0,%1,%2,%3}, {%4,%5,%6,%7}, {%8,%9}, {%0,%1,%2,%3};"
        : "+f"(d[0]), "+f"(d[1]), "+f"(d[2]), "+f"(d[3])
        : "r"(__float_as_uint(a[0])), "r"(__float_as_uint(a[1])),
          "r"(__float_as_uint(a[2])), "r"(__float_as_uint(a[3])),
          "r"(__float_as_uint(bx)), "r"(__float_as_uint(by)));
}

__device__ __forceinline__ uint32_t smem_u32(const void* p) {
    uint32_t a;
    asm("{ .reg .u64 t; cvta.to.shared.u64 t, %1; cvt.u32.u64 %0, t; }" : "=r"(a) : "l"(p));
    return a;
}
__device__ __forceinline__ void cpasync16(uint32_t dst, const void* src) {
    asm volatile("cp.async.cg.shared.global [%0], [%1], 16;" :: "r"(dst), "l"(src));
}
#define CP_COMMIT() asm volatile("cp.async.commit_group;" ::: "memory")
#define CP_WAIT(n)  asm volatile("cp.async.wait_group %0;" :: "n"(n) : "memory")

// scatter one tf32-rounded float4 of row `row`, k-chunk kc, quad c4 into afrag
__device__ __forceinline__ void scatterA(float* __restrict__ afrag, int row, int kc,
                                         int c4, const float* vv)
{
    int mt = row >> 7, r127 = row & 127;
    int mi = r127 >> 4, m16 = r127 & 15;
    int ga = m16 & 7, rA = m16 >> 3;
    int ki = c4 >> 1, khi = c4 & 1;
    float* dst = afrag + ((size_t)mt * KC_D + kc) * 4096;
    int base = ((mi * 4 + ki) * 32) * 4 + (rA + 2 * khi);
#pragma unroll
    for (int e = 0; e < 4; e++)
        dst[base + ((ga * 4 + e) ^ ki) * 4] = vv[e];
}

// =================== prelayout kernels ======================================
__global__ void __launch_bounds__(256)
prelayout_A(const float* __restrict__ A, float* __restrict__ out, int K)
{
    const int kc = blockIdx.x;
    const int mt = blockIdx.y;
    const int t  = threadIdx.x;
    float* dst = out + ((size_t)mt * gridDim.x + kc) * 4096;
#pragma unroll
    for (int i = 0; i < 4; i++) {
        int idx = t + i * 256;
        int row = idx >> 3, c4 = idx & 7;
        int mi = row >> 4, m16 = row & 15;
        int ga = m16 & 7, rA = m16 >> 3;
        int ki = c4 >> 1, khi = c4 & 1;
        int base = ((mi * 4 + ki) * 32) * 4 + (rA + 2 * khi);
        float4 v = *(const float4*)(A + (size_t)(mt * 128 + row) * K + kc * 32 + c4 * 4);
        float vv[4] = {tf32r(v.x), tf32r(v.y), tf32r(v.z), tf32r(v.w)};
#pragma unroll
        for (int e = 0; e < 4; e++) {
            int lp = (ga * 4 + e) ^ ki;
            dst[base + lp * 4] = vv[e];
        }
    }
}

// generic W scatter body: one (kc, nt) chunk of W[K,N] row-major
__device__ __forceinline__ void prelayout_W_body(
    const float* __restrict__ W, float* __restrict__ dst, int N, int kc, int nt)
{
    const int t = threadIdx.x;
#pragma unroll
    for (int i = 0; i < 4; i++) {
        int idx = t + i * 256;
        int rowk = idx >> 5, c4 = idx & 31;
        int n0 = c4 * 4;
        int ki = rowk >> 3, kk = rowk & 7;
        int tgb = kk & 3, hi = kk >> 2;
        int ni = n0 >> 3, g0 = n0 & 7;
        int swz = ((ni & 3) << 3) ^ (((ni >> 2) & 3) << 1);
        int ln0 = g0 * 4 + tgb;
        int base = ((ni * 4 + ki) * 32) * 2 + hi;
        float4 v = *(const float4*)(W + (size_t)(kc * 32 + rowk) * N + nt * 128 + n0);
        float vv[4] = {tf32r(v.x), tf32r(v.y), tf32r(v.z), tf32r(v.w)};
#pragma unroll
        for (int e = 0; e < 4; e++) {
            int lp = (ln0 + 4 * e) ^ swz;
            dst[base + lp * 2] = vv[e];
        }
    }
}

__global__ void __launch_bounds__(256)
prelayout_W(const float* __restrict__ W, float* __restrict__ out, int N)
{
    float* dst = out + ((size_t)blockIdx.y * gridDim.x + blockIdx.x) * 4096;
    prelayout_W_body(W, dst, N, blockIdx.x, blockIdx.y);
}

// ALL 16 layer weight matrices in one launch: grid (KC_D, NT_D, LL*4)
__global__ void __launch_bounds__(256)
prelayout_W_all(const float* __restrict__ qw, const float* __restrict__ kw,
                const float* __restrict__ vw, const float* __restrict__ ow,
                float* __restrict__ out)
{
    const int z = blockIdx.z;                 // 0..15
    const int l = z >> 2, m = z & 3;
    const float* base = (m == 0) ? qw : (m == 1) ? kw : (m == 2) ? vw : ow;
    const float* W = base + (size_t)l * DD * DD;
    float* dst = out + ((size_t)z * NT_D * KC_D
                        + (size_t)blockIdx.y * KC_D + blockIdx.x) * 4096;
    prelayout_W_body(W, dst, DD, blockIdx.x, blockIdx.y);
}

// ============== GEMM on prelaid operands, cp.async 3-stage ring =============
#define PSTAGES 3
#define STAGE_FLOATS 8192
#define GEMM_PRE_SMEM_BYTES (PSTAGES * STAGE_FLOATS * 4)   // 96 KB

__device__ __forceinline__ void gemm_pre_core(
    const float* __restrict__ aSrc, const float* __restrict__ bSrc,
    const float* __restrict__ bias, float* __restrict__ C,
    int N, int nkc, int mt, int nt, float* sm)
{
    const int t    = threadIdx.x;
    const int lane = t & 31;
    const int wid  = t >> 5;
    const int g    = lane >> 2;
    const int tg   = lane & 3;
    const int wm   = (wid & 1) * 64;
    const int wn   = (wid >> 1) * 32;
    const uint32_t smb = smem_u32(sm);

    float acc[4][4][4];
#pragma unroll
    for (int mf = 0; mf < 4; mf++)
#pragma unroll
        for (int nf = 0; nf < 4; nf++)
#pragma unroll
            for (int r = 0; r < 4; r++) acc[mf][nf][r] = 0.0f;

    auto issue = [&](int c) {
        uint32_t dstA = smb + (uint32_t)((c % PSTAGES) * STAGE_FLOATS) * 4u;
        uint32_t dstB = dstA + 4096u * 4u;
        const float* sa = aSrc + (size_t)c * 4096;
        const float* sb = bSrc + (size_t)c * 4096;
#pragma unroll
        for (int i = 0; i < 4; i++) {
            int o4 = (t + i * 256) * 4;
            cpasync16(dstA + (uint32_t)o4 * 4u, sa + o4);
            cpasync16(dstB + (uint32_t)o4 * 4u, sb + o4);
        }
        CP_COMMIT();
    };

    issue(0);
    issue(1);

    int bswz[4];
#pragma unroll
    for (int nf = 0; nf < 4; nf++) {
        int ni = (wid >> 1) * 4 + nf;
        bswz[nf] = lane ^ ((ni & 3) << 3) ^ (((ni >> 2) & 3) << 1);
    }

    for (int kt = 0; kt < nkc; kt++) {
        if (kt + 1 < nkc) { CP_WAIT(1); } else { CP_WAIT(0); }
        __syncthreads();
        if (kt + 2 < nkc) issue(kt + 2);

        const float* asb = sm + (kt % PSTAGES) * STAGE_FLOATS;
        const float* bsb = asb + 4096;
#pragma unroll
        for (int ki = 0; ki < 4; ki++) {
            float4 afv[4];
            float2 bfv[4];
#pragma unroll
            for (int mf = 0; mf < 4; mf++) {
                int mi = (wid & 1) * 4 + mf;
                afv[mf] = *(const float4*)(asb + ((mi * 4 + ki) * 32 + (lane ^ ki)) * 4);
            }
#pragma unroll
            for (int nf = 0; nf < 4; nf++) {
                int ni = (wid >> 1) * 4 + nf;
                bfv[nf] = *(const float2*)(bsb + ((ni * 4 + ki) * 32 + bswz[nf]) * 2);
            }
#pragma unroll
            for (int mf = 0; mf < 4; mf++)
#pragma unroll
                for (int nf = 0; nf < 4; nf++)
                    mma16n8k8(acc[mf][nf], (const float*)&afv[mf], bfv[nf].x, bfv[nf].y);
        }
    }

#pragma unroll
    for (int mf = 0; mf < 4; mf++) {
        const int r0 = mt * 128 + wm + mf * 16 + g;
        const int r1 = r0 + 8;
#pragma unroll
        for (int nf = 0; nf < 4; nf++) {
            const int col = nt * 128 + wn + nf * 8 + tg * 2;
            const float b0 = bias[col], b1 = bias[col + 1];
            float2 v0 = make_float2(acc[mf][nf][0] + b0, acc[mf][nf][1] + b1);
            float2 v1 = make_float2(acc[mf][nf][2] + b0, acc[mf][nf][3] + b1);
            *(float2*)(C + (size_t)r0 * N + col) = v0;
            *(float2*)(C + (size_t)r1 * N + col) = v1;
        }
    }
}

__global__ void __launch_bounds__(256, 2)
gemm_pre(const float* __restrict__ afrag, const float* __restrict__ wfrag,
         const float* __restrict__ bias, float* __restrict__ C,
         int N, int nkc)
{
    extern __shared__ float sm[];
    const int mt = blockIdx.x, nt = blockIdx.y;
    gemm_pre_core(afrag + (size_t)mt * nkc * 4096,
                  wfrag + (size_t)nt * nkc * 4096,
                  bias, C, N, nkc, mt, nt, sm);
}

__global__ void __launch_bounds__(256, 2)
gemm_pre_qkv(const float* __restrict__ afrag,
             const float* __restrict__ qwf, const float* __restrict__ kwf,
             const float* __restrict__ vwf,
             const float* __restrict__ qb, const float* __restrict__ kb,
             const float* __restrict__ vb,
             float* __restrict__ qo, float* __restrict__ ko, float* __restrict__ vo)
{
    extern __shared__ float sm[];
    const int mt = blockIdx.x, nt = blockIdx.y;
    const float* wf   = (blockIdx.z == 0) ? qwf : (blockIdx.z == 1) ? kwf : vwf;
    const float* bias = (blockIdx.z == 0) ? qb  : (blockIdx.z == 1) ? kb  : vb;
    float*       C    = (blockIdx.z == 0) ? qo  : (blockIdx.z == 1) ? ko  : vo;
    gemm_pre_core(afrag + (size_t)mt * KC_D * 4096,
                  wf    + (size_t)nt * KC_D * 4096,
                  bias, C, DD, KC_D, mt, nt, sm);
}

// -------- embedding + positional encoding; also emits fragment-major x -----
__global__ void __launch_bounds__(256)
embed_kernel(const int* __restrict__ tokens, const float* __restrict__ emb,
             float* __restrict__ x, float* __restrict__ afrag)
{
    int row = blockIdx.x;
    int pos = row & (SS - 1);
    int tok = tokens[row];
    const float* e = emb + (size_t)tok * DD;
    float* xr = x + (size_t)row * DD;
    const float c = -logf(10000.0f) / (float)DD;
    const int d0 = threadIdx.x * 4;
    float vv[4];
#pragma unroll
    for (int j = 0; j < 4; j++) {
        int d = d0 + j;
        int i = d >> 1;
        float ang = (float)pos * expf((float)(2 * i) * c);
        float pe = (d & 1) ? cosf(ang) : sinf(ang);
        vv[j] = e[d] + pe;
    }
    *(float4*)(xr + d0) = *(float4*)vv;
    float tv[4] = {tf32r(vv[0]), tf32r(vv[1]), tf32r(vv[2]), tf32r(vv[3])};
    scatterA(afrag, row, d0 >> 5, (d0 & 31) >> 2, tv);
}

// ============= tensor-core causal flash attention (tf32 mma) ================
// 256 threads = 8 warps; warp owns 16 query rows.
__global__ void __launch_bounds__(256)
attn_mma_kernel(const float* __restrict__ Q, const float* __restrict__ K,
                const float* __restrict__ V, float* __restrict__ O)
{
    __shared__ __align__(16) float Ks[32][68];
    __shared__ __align__(16) float Vs[32][72];
    __shared__ __align__(16) float Ps[8][16][36];

    const int b  = blockIdx.z;
    const int h  = blockIdx.y;
    const int qb = blockIdx.x * 128;
    const int tid = threadIdx.x;
    const int w    = tid >> 5;
    const int lane = tid & 31;
    const int g    = lane >> 2;
    const int tg   = lane & 3;
    const size_t base = (size_t)(b * SS) * DD + (size_t)h * HD;

    float qf[8][4];
    {
        const int r0 = qb + w * 16 + g;
        const int r1 = r0 + 8;
#pragma unroll
        for (int k8 = 0; k8 < 8; k8++) {
            int k0 = k8 * 8;
            qf[k8][0] = tf32r(Q[base + (size_t)r0 * DD + k0 + tg]     * 0.125f);
            qf[k8][1] = tf32r(Q[base + (size_t)r1 * DD + k0 + tg]     * 0.125f);
            qf[k8][2] = tf32r(Q[base + (size_t)r0 * DD + k0 + tg + 4] * 0.125f);
            qf[k8][3] = tf32r(Q[base + (size_t)r1 * DD + k0 + tg + 4] * 0.125f);
        }
    }

    float oacc[8][4];
#pragma unroll
    for (int nf = 0; nf < 8; nf++)
#pragma unroll
        for (int r = 0; r < 4; r++) oacc[nf][r] = 0.0f;
    float m0 = -1e30f, m1 = -1e30f, l0 = 0.0f, l1 = 0.0f;

    const int qmax_w = qb + w * 16 + 15;
    const int kend = qb + 128;
    for (int kt = 0; kt < kend; kt += 32) {
#pragma unroll
        for (int i = 0; i < 2; i++) {
            int idx4 = tid + i * 256;
            int r = idx4 >> 4;
            int c = (idx4 & 15) * 4;
            size_t ga = base + (size_t)(kt + r) * DD + c;
            float4 kv = *(const float4*)(K + ga);
            float4 vv = *(const float4*)(V + ga);
            Ks[r][c]   = tf32r(kv.x); Ks[r][c+1] = tf32r(kv.y);
            Ks[r][c+2] = tf32r(kv.z); Ks[r][c+3] = tf32r(kv.w);
            Vs[r][c]   = tf32r(vv.x); Vs[r][c+1] = tf32r(vv.y);
            Vs[r][c+2] = tf32r(vv.z); Vs[r][c+3] = tf32r(vv.w);
        }
        __syncthreads();

        if (kt <= qmax_w) {
            float sacc[4][4];
#pragma unroll
            for (int nf = 0; nf < 4; nf++)
#pragma unroll
                for (int r = 0; r < 4; r++) sacc[nf][r] = 0.0f;
#pragma unroll
            for (int k8 = 0; k8 < 8; k8++) {
                float2 bf[4];
#pragma unroll
                for (int nf = 0; nf < 4; nf++) {
                    bf[nf].x = Ks[nf * 8 + g][k8 * 8 + tg];
                    bf[nf].y = Ks[nf * 8 + g][k8 * 8 + tg + 4];
                }
#pragma unroll
                for (int nf = 0; nf < 4; nf++)
                    mma16n8k8(sacc[nf], qf[k8], bf[nf].x, bf[nf].y);
            }

            const int row0 = qb + w * 16 + g;
            const int row1 = row0 + 8;
#pragma unroll
            for (int nf = 0; nf < 4; nf++) {
#pragma unroll
                for (int e = 0; e < 2; e++) {
                    int key = kt + nf * 8 + tg * 2 + e;
                    if (key > row0) sacc[nf][e]     = -1e30f;
                    if (key > row1) sacc[nf][2 + e] = -1e30f;
                }
            }
            float t0 = -1e30f, t1 = -1e30f;
#pragma unroll
            for (int nf = 0; nf < 4; nf++) {
                t0 = fmaxf(t0, fmaxf(sacc[nf][0], sacc[nf][1]));
                t1 = fmaxf(t1, fmaxf(sacc[nf][2], sacc[nf][3]));
            }
            t0 = fmaxf(t0, __shfl_xor_sync(0xFFFFFFFFu, t0, 1));
            t0 = fmaxf(t0, __shfl_xor_sync(0xFFFFFFFFu, t0, 2));
            t1 = fmaxf(t1, __shfl_xor_sync(0xFFFFFFFFu, t1, 1));
            t1 = fmaxf(t1, __shfl_xor_sync(0xFFFFFFFFu, t1, 2));
            float nm0 = fmaxf(m0, t0);
            float nm1 = fmaxf(m1, t1);
            float c0 = __expf(m0 - nm0);
            float c1 = __expf(m1 - nm1);
            m0 = nm0; m1 = nm1;

            float ps0 = 0.0f, ps1 = 0.0f;
#pragma unroll
            for (int nf = 0; nf < 4; nf++) {
#pragma unroll
                for (int e = 0; e < 2; e++) {
                    float p0 = __expf(sacc[nf][e]     - nm0);
                    float p1 = __expf(sacc[nf][2 + e] - nm1);
                    sacc[nf][e]     = p0;
                    sacc[nf][2 + e] = p1;
                    ps0 += p0; ps1 += p1;
                }
            }
            ps0 += __shfl_xor_sync(0xFFFFFFFFu, ps0, 1);
            ps0 += __shfl_xor_sync(0xFFFFFFFFu, ps0, 2);
            ps1 += __shfl_xor_sync(0xFFFFFFFFu, ps1, 1);
            ps1 += __shfl_xor_sync(0xFFFFFFFFu, ps1, 2);
            l0 = l0 * c0 + ps0;
            l1 = l1 * c1 + ps1;

#pragma unroll
            for (int nf2 = 0; nf2 < 8; nf2++) {
                oacc[nf2][0] *= c0; oacc[nf2][1] *= c0;
                oacc[nf2][2] *= c1; oacc[nf2][3] *= c1;
            }
#pragma unroll
            for (int nf = 0; nf < 4; nf++) {
                float2 lo = make_float2(tf32r(sacc[nf][0]), tf32r(sacc[nf][1]));
                float2 hi = make_float2(tf32r(sacc[nf][2]), tf32r(sacc[nf][3]));
                *(float2*)&Ps[w][g][nf * 8 + tg * 2]     = lo;
                *(float2*)&Ps[w][g + 8][nf * 8 + tg * 2] = hi;
            }
            __syncwarp();

#pragma unroll
            for (int kk = 0; kk < 4; kk++) {
                float af[4];
                af[0] = Ps[w][g][kk * 8 + tg];
                af[1] = Ps[w][g + 8][kk * 8 + tg];
                af[2] = Ps[w][g][kk * 8 + tg + 4];
                af[3] = Ps[w][g + 8][kk * 8 + tg + 4];
#pragma unroll
                for (int nf2 = 0; nf2 < 8; nf2++) {
                    float bx = Vs[kk * 8 + tg][nf2 * 8 + g];
                    float by = Vs[kk * 8 + tg + 4][nf2 * 8 + g];
                    mma16n8k8(oacc[nf2], af, bx, by);
                }
            }
        }
        __syncthreads();
    }

    {
        const int row0 = qb + w * 16 + g;
        const int row1 = row0 + 8;
        const float inv0 = 1.0f / l0;
        const float inv1 = 1.0f / l1;
#pragma unroll
        for (int nf2 = 0; nf2 < 8; nf2++) {
            const int col = nf2 * 8 + tg * 2;
            float2 v0 = make_float2(oacc[nf2][0] * inv0, oacc[nf2][1] * inv0);
            float2 v1 = make_float2(oacc[nf2][2] * inv1, oacc[nf2][3] * inv1);
            *(float2*)(O + base + (size_t)row0 * DD + col) = v0;
            *(float2*)(O + base + (size_t)row1 * DD + col) = v1;
        }
    }
}

// ------- residual add + layernorm; also emits fragment-major x -------------
__global__ void __launch_bounds__(256)
ln_res_kernel(float* __restrict__ x, const float* __restrict__ res,
              const float* __restrict__ g, const float* __restrict__ beta,
              float* __restrict__ afrag)
{
    __shared__ float red[256];
    const int row = blockIdx.x;
    const int tid = threadIdx.x;
    const int d0  = tid * 4;
    float* xr = x + (size_t)row * DD;
    const float* rr = res + (size_t)row * DD;

    float y[4];
    float s = 0.0f;
    {
        float4 xv = *(const float4*)(xr + d0);
        float4 rv = *(const float4*)(rr + d0);
        y[0] = xv.x + rv.x; y[1] = xv.y + rv.y;
        y[2] = xv.z + rv.z; y[3] = xv.w + rv.w;
        s = y[0] + y[1] + y[2] + y[3];
    }
    red[tid] = s; __syncthreads();
    for (int off = 128; off > 0; off >>= 1) {
        if (tid < off) red[tid] += red[tid + off];
        __syncthreads();
    }
    float mu = red[0] * (1.0f / (float)DD);
    __syncthreads();

    float vs = 0.0f;
#pragma unroll
    for (int i = 0; i < 4; i++) {
        float d2 = y[i] - mu;
        vs += d2 * d2;
    }
    red[tid] = vs; __syncthreads();
    for (int off = 128; off > 0; off >>= 1) {
        if (tid < off) red[tid] += red[tid + off];
        __syncthreads();
    }
    float var = red[0] * (1.0f / (float)DD);
    float inv = rsqrtf(var + 1e-5f);

    float out[4];
#pragma unroll
    for (int i = 0; i < 4; i++)
        out[i] = (y[i] - mu) * inv * g[d0 + i] + beta[d0 + i];
    *(float4*)(xr + d0) = *(float4*)out;
    float tv[4] = {tf32r(out[0]), tf32r(out[1]), tf32r(out[2]), tf32r(out[3])};
    scatterA(afrag, row, d0 >> 5, (d0 & 31) >> 2, tv);
}

// ---------------------------------------------------------------------------
extern "C" void kernel_launch(void* const* d_in, const int* in_sizes, int n_in,
                              void* d_out, int out_size)
{
    const int*   tokens = (const int*)  d_in[0];
    const float* emb    = (const float*)d_in[1];
    const float* qw     = (const float*)d_in[2];
    const float* qb     = (const float*)d_in[3];
    const float* kw     = (const float*)d_in[4];
    const float* kb     = (const float*)d_in[5];
    const float* vw     = (const float*)d_in[6];
    const float* vb     = (const float*)d_in[7];
    const float* ow     = (const float*)d_in[8];
    const float* ob     = (const float*)d_in[9];
    const float* ln_g   = (const float*)d_in[10];
    const float* ln_b   = (const float*)d_in[11];
    const float* out_w  = (const float*)d_in[12];
    const float* out_b  = (const float*)d_in[13];
    float* logits = (float*)d_out;

    float *x, *q, *k, *v, *ctx, *attn, *afrag, *wfrag, *lwf;
    cudaGetSymbolAddress((void**)&x,     g_x);
    cudaGetSymbolAddress((void**)&q,     g_q);
    cudaGetSymbolAddress((void**)&k,     g_k);
    cudaGetSymbolAddress((void**)&v,     g_v);
    cudaGetSymbolAddress((void**)&ctx,   g_ctx);
    cudaGetSymbolAddress((void**)&attn,  g_attn);
    cudaGetSymbolAddress((void**)&afrag, g_afrag);
    cudaGetSymbolAddress((void**)&wfrag, g_wfrag);
    cudaGetSymbolAddress((void**)&lwf,   g_lwf);

    cudaFuncSetAttribute(gemm_pre,     cudaFuncAttributeMaxDynamicSharedMemorySize, GEMM_PRE_SMEM_BYTES);
    cudaFuncSetAttribute(gemm_pre_qkv, cudaFuncAttributeMaxDynamicSharedMemorySize, GEMM_PRE_SMEM_BYTES);

    const size_t WMAT = (size_t)NT_D * KC_D * 4096;

    // weight prelayouts: logits (one launch) + ALL 16 layer mats (one launch)
    {
        dim3 gw(KC_D, NT_OUT);
        prelayout_W<<<gw, 256>>>(out_w, wfrag, VV);
        dim3 gall(KC_D, NT_D, LL * 4);    // (32, 8, 16)
        prelayout_W_all<<<gall, 256>>>(qw, kw, vw, ow, lwf);
    }

    // embed writes x AND fragment-major afrag
    embed_kernel<<<NROW, 256>>>(tokens, emb, x, afrag);

    dim3 gpreA(KC_D, MT_A);               // (32, 16)
    dim3 gqkv(MT_A, NT_D, 3);             // (16, 8, 3)
    dim3 gproj(MT_A, NT_D);               // (16, 8)
    dim3 gattn(SS / 128, HH, BB);         // (8, 16, 2)

    for (int l = 0; l < LL; l++) {
        size_t bo = (size_t)l * DD;
        gemm_pre_qkv<<<gqkv, 256, GEMM_PRE_SMEM_BYTES>>>(
            afrag,
            lwf + (size_t)(l * 4 + 0) * WMAT,
            lwf + (size_t)(l * 4 + 1) * WMAT,
            lwf + (size_t)(l * 4 + 2) * WMAT,
            qb + bo, kb + bo, vb + bo, q, k, v);
        attn_mma_kernel<<<gattn, 256>>>(q, k, v, ctx);
        prelayout_A<<<gpreA, 256>>>(ctx, afrag, DD);
        gemm_pre<<<gproj, 256, GEMM_PRE_SMEM_BYTES>>>(
            afrag, lwf + (size_t)(l * 4 + 3) * WMAT, ob + bo, attn, DD, KC_D);
        ln_res_kernel<<<NROW, 256>>>(x, attn, ln_g + bo, ln_b + bo, afrag);
    }

    // final logits
    dim3 gout(MT_A, NT_OUT);              // (16, 250)
    gemm_pre<<<gout, 256, GEMM_PRE_SMEM_BYTES>>>(afrag, wfrag, out_b, logits, VV, KC_D);
}

// round 15
// speedup vs baseline: 1.0494x; 1.0279x over previous
#include <cuda_runtime.h>
#include <cstdint>
#include <math.h>

#define BB 2
#define SS 1024
#define DD 1024
#define HH 16
#define HD 64
#define LL 4
#define VV 32000
#define NROW (BB * SS)      // 2048
#define NT_OUT (VV / 128)   // 250
#define NT_D   (DD / 128)   // 8
#define MT_A   (NROW / 128) // 16
#define KC_D   (DD / 32)    // 32

// ---------------- scratch (static device globals; no allocs allowed) --------
__device__ float g_x[NROW * DD];
__device__ float g_q[NROW * DD];
__device__ float g_k[NROW * DD];
__device__ float g_v[NROW * DD];
__device__ float g_attn[NROW * DD];
__device__ float g_afrag[MT_A * KC_D * 4096];                       // 8 MB
__device__ float g_wfrag[(size_t)NT_OUT * KC_D * 4096];             // 131 MB
__device__ float g_lwf[(size_t)LL * 4 * NT_D * KC_D * 4096];        // 64 MB

__device__ __forceinline__ float tf32r(float x) {
    float r; asm("cvt.rna.tf32.f32 %0, %1;" : "=f"(r) : "f"(x)); return r;
}

__device__ __forceinline__ void mma16n8k8(float* d, const float* a, float bx, float by) {
    asm volatile(
        "mma.sync.aligned.m16n8k8.row.col.f32.tf32.tf32.f32 "
        "{%0,%1,%2,%3}, {%4,%5,%6,%7}, {%8,%9}, {%0,%1,%2,%3};"
        : "+f"(d[0]), "+f"(d[1]), "+f"(d[2]), "+f"(d[3])
        : "r"(__float_as_uint(a[0])), "r"(__float_as_uint(a[1])),
          "r"(__float_as_uint(a[2])), "r"(__float_as_uint(a[3])),
          "r"(__float_as_uint(bx)), "r"(__float_as_uint(by)));
}

__device__ __forceinline__ uint32_t smem_u32(const void* p) {
    uint32_t a;
    asm("{ .reg .u64 t; cvta.to.shared.u64 t, %1; cvt.u32.u64 %0, t; }" : "=r"(a) : "l"(p));
    return a;
}
__device__ __forceinline__ void cpasync16(uint32_t dst, const void* src) {
    asm volatile("cp.async.cg.shared.global [%0], [%1], 16;" :: "r"(dst), "l"(src));
}
#define CP_COMMIT() asm volatile("cp.async.commit_group;" ::: "memory")
#define CP_WAIT(n)  asm volatile("cp.async.wait_group %0;" :: "n"(n) : "memory")

// scatter one tf32-rounded float4 of row `row`, k-chunk kc, quad c4 into afrag
__device__ __forceinline__ void scatterA(float* __restrict__ afrag, int row, int kc,
                                         int c4, const float* vv)
{
    int mt = row >> 7, r127 = row & 127;
    int mi = r127 >> 4, m16 = r127 & 15;
    int ga = m16 & 7, rA = m16 >> 3;
    int ki = c4 >> 1, khi = c4 & 1;
    float* dst = afrag + ((size_t)mt * KC_D + kc) * 4096;
    int base = ((mi * 4 + ki) * 32) * 4 + (rA + 2 * khi);
#pragma unroll
    for (int e = 0; e < 4; e++)
        dst[base + ((ga * 4 + e) ^ ki) * 4] = vv[e];
}

// single-element scatter: value at (row, global col)
__device__ __forceinline__ void scatterA1(float* __restrict__ afrag, int row, int col,
                                          float val)
{
    int mt = row >> 7, r127 = row & 127;
    int mi = r127 >> 4, m16 = r127 & 15;
    int ga = m16 & 7, rA = m16 >> 3;
    int kc = col >> 5;
    int c4 = (col & 31) >> 2;
    int ki = c4 >> 1, khi = c4 & 1;
    int e  = col & 3;
    float* dst = afrag + ((size_t)mt * KC_D + kc) * 4096;
    int idx = ((mi * 4 + ki) * 32) * 4 + (rA + 2 * khi) + ((ga * 4 + e) ^ ki) * 4;
    dst[idx] = val;
}

// =================== prelayout kernels ======================================
// generic W scatter body: one (kc, nt) chunk of W[K,N] row-major
__device__ __forceinline__ void prelayout_W_body(
    const float* __restrict__ W, float* __restrict__ dst, int N, int kc, int nt)
{
    const int t = threadIdx.x;
#pragma unroll
    for (int i = 0; i < 4; i++) {
        int idx = t + i * 256;
        int rowk = idx >> 5, c4 = idx & 31;
        int n0 = c4 * 4;
        int ki = rowk >> 3, kk = rowk & 7;
        int tgb = kk & 3, hi = kk >> 2;
        int ni = n0 >> 3, g0 = n0 & 7;
        int swz = ((ni & 3) << 3) ^ (((ni >> 2) & 3) << 1);
        int ln0 = g0 * 4 + tgb;
        int base = ((ni * 4 + ki) * 32) * 2 + hi;
        float4 v = *(const float4*)(W + (size_t)(kc * 32 + rowk) * N + nt * 128 + n0);
        float vv[4] = {tf32r(v.x), tf32r(v.y), tf32r(v.z), tf32r(v.w)};
#pragma unroll
        for (int e = 0; e < 4; e++) {
            int lp = (ln0 + 4 * e) ^ swz;
            dst[base + lp * 2] = vv[e];
        }
    }
}

__global__ void __launch_bounds__(256)
prelayout_W(const float* __restrict__ W, float* __restrict__ out, int N)
{
    float* dst = out + ((size_t)blockIdx.y * gridDim.x + blockIdx.x) * 4096;
    prelayout_W_body(W, dst, N, blockIdx.x, blockIdx.y);
}

// ALL 16 layer weight matrices in one launch: grid (KC_D, NT_D, LL*4)
__global__ void __launch_bounds__(256)
prelayout_W_all(const float* __restrict__ qw, const float* __restrict__ kw,
                const float* __restrict__ vw, const float* __restrict__ ow,
                float* __restrict__ out)
{
    const int z = blockIdx.z;
    const int l = z >> 2, m = z & 3;
    const float* base = (m == 0) ? qw : (m == 1) ? kw : (m == 2) ? vw : ow;
    const float* W = base + (size_t)l * DD * DD;
    float* dst = out + ((size_t)z * NT_D * KC_D
                        + (size_t)blockIdx.y * KC_D + blockIdx.x) * 4096;
    prelayout_W_body(W, dst, DD, blockIdx.x, blockIdx.y);
}

// ============== GEMM on prelaid operands, cp.async 3-stage ring =============
#define PSTAGES 3
#define STAGE_FLOATS 8192
#define GEMM_PRE_SMEM_BYTES (PSTAGES * STAGE_FLOATS * 4)   // 96 KB

__device__ __forceinline__ void gemm_pre_core(
    const float* __restrict__ aSrc, const float* __restrict__ bSrc,
    const float* __restrict__ bias, float* __restrict__ C,
    int N, int nkc, int mt, int nt, float* sm)
{
    const int t    = threadIdx.x;
    const int lane = t & 31;
    const int wid  = t >> 5;
    const int g    = lane >> 2;
    const int tg   = lane & 3;
    const int wm   = (wid & 1) * 64;
    const int wn   = (wid >> 1) * 32;
    const uint32_t smb = smem_u32(sm);

    float acc[4][4][4];
#pragma unroll
    for (int mf = 0; mf < 4; mf++)
#pragma unroll
        for (int nf = 0; nf < 4; nf++)
#pragma unroll
            for (int r = 0; r < 4; r++) acc[mf][nf][r] = 0.0f;

    auto issue = [&](int c) {
        uint32_t dstA = smb + (uint32_t)((c % PSTAGES) * STAGE_FLOATS) * 4u;
        uint32_t dstB = dstA + 4096u * 4u;
        const float* sa = aSrc + (size_t)c * 4096;
        const float* sb = bSrc + (size_t)c * 4096;
#pragma unroll
        for (int i = 0; i < 4; i++) {
            int o4 = (t + i * 256) * 4;
            cpasync16(dstA + (uint32_t)o4 * 4u, sa + o4);
            cpasync16(dstB + (uint32_t)o4 * 4u, sb + o4);
        }
        CP_COMMIT();
    };

    issue(0);
    issue(1);

    int bswz[4];
#pragma unroll
    for (int nf = 0; nf < 4; nf++) {
        int ni = (wid >> 1) * 4 + nf;
        bswz[nf] = lane ^ ((ni & 3) << 3) ^ (((ni >> 2) & 3) << 1);
    }

    for (int kt = 0; kt < nkc; kt++) {
        if (kt + 1 < nkc) { CP_WAIT(1); } else { CP_WAIT(0); }
        __syncthreads();
        if (kt + 2 < nkc) issue(kt + 2);

        const float* asb = sm + (kt % PSTAGES) * STAGE_FLOATS;
        const float* bsb = asb + 4096;
#pragma unroll
        for (int ki = 0; ki < 4; ki++) {
            float4 afv[4];
            float2 bfv[4];
#pragma unroll
            for (int mf = 0; mf < 4; mf++) {
                int mi = (wid & 1) * 4 + mf;
                afv[mf] = *(const float4*)(asb + ((mi * 4 + ki) * 32 + (lane ^ ki)) * 4);
            }
#pragma unroll
            for (int nf = 0; nf < 4; nf++) {
                int ni = (wid >> 1) * 4 + nf;
                bfv[nf] = *(const float2*)(bsb + ((ni * 4 + ki) * 32 + bswz[nf]) * 2);
            }
#pragma unroll
            for (int mf = 0; mf < 4; mf++)
#pragma unroll
                for (int nf = 0; nf < 4; nf++)
                    mma16n8k8(acc[mf][nf], (const float*)&afv[mf], bfv[nf].x, bfv[nf].y);
        }
    }

#pragma unroll
    for (int mf = 0; mf < 4; mf++) {
        const int r0 = mt * 128 + wm + mf * 16 + g;
        const int r1 = r0 + 8;
#pragma unroll
        for (int nf = 0; nf < 4; nf++) {
            const int col = nt * 128 + wn + nf * 8 + tg * 2;
            const float b0 = bias[col], b1 = bias[col + 1];
            float2 v0 = make_float2(acc[mf][nf][0] + b0, acc[mf][nf][1] + b1);
            float2 v1 = make_float2(acc[mf][nf][2] + b0, acc[mf][nf][3] + b1);
            *(float2*)(C + (size_t)r0 * N + col) = v0;
            *(float2*)(C + (size_t)r1 * N + col) = v1;
        }
    }
}

__global__ void __launch_bounds__(256, 2)
gemm_pre(const float* __restrict__ afrag, const float* __restrict__ wfrag,
         const float* __restrict__ bias, float* __restrict__ C,
         int N, int nkc)
{
    extern __shared__ float sm[];
    const int mt = blockIdx.x, nt = blockIdx.y;
    gemm_pre_core(afrag + (size_t)mt * nkc * 4096,
                  wfrag + (size_t)nt * nkc * 4096,
                  bias, C, N, nkc, mt, nt, sm);
}

__global__ void __launch_bounds__(256, 2)
gemm_pre_qkv(const float* __restrict__ afrag,
             const float* __restrict__ qwf, const float* __restrict__ kwf,
             const float* __restrict__ vwf,
             const float* __restrict__ qb, const float* __restrict__ kb,
             const float* __restrict__ vb,
             float* __restrict__ qo, float* __restrict__ ko, float* __restrict__ vo)
{
    extern __shared__ float sm[];
    const int mt = blockIdx.x, nt = blockIdx.y;
    const float* wf   = (blockIdx.z == 0) ? qwf : (blockIdx.z == 1) ? kwf : vwf;
    const float* bias = (blockIdx.z == 0) ? qb  : (blockIdx.z == 1) ? kb  : vb;
    float*       C    = (blockIdx.z == 0) ? qo  : (blockIdx.z == 1) ? ko  : vo;
    gemm_pre_core(afrag + (size_t)mt * KC_D * 4096,
                  wf    + (size_t)nt * KC_D * 4096,
                  bias, C, DD, KC_D, mt, nt, sm);
}

// -------- embedding + positional encoding; also emits fragment-major x -----
__global__ void __launch_bounds__(256)
embed_kernel(const int* __restrict__ tokens, const float* __restrict__ emb,
             float* __restrict__ x, float* __restrict__ afrag)
{
    int row = blockIdx.x;
    int pos = row & (SS - 1);
    int tok = tokens[row];
    const float* e = emb + (size_t)tok * DD;
    float* xr = x + (size_t)row * DD;
    const float c = -logf(10000.0f) / (float)DD;
    const int d0 = threadIdx.x * 4;
    float vv[4];
#pragma unroll
    for (int j = 0; j < 4; j++) {
        int d = d0 + j;
        int i = d >> 1;
        float ang = (float)pos * expf((float)(2 * i) * c);
        float pe = (d & 1) ? cosf(ang) : sinf(ang);
        vv[j] = e[d] + pe;
    }
    *(float4*)(xr + d0) = *(float4*)vv;
    float tv[4] = {tf32r(vv[0]), tf32r(vv[1]), tf32r(vv[2]), tf32r(vv[3])};
    scatterA(afrag, row, d0 >> 5, (d0 & 31) >> 2, tv);
}

// ============= tensor-core causal flash attention (tf32 mma) ================
// 256 threads = 8 warps; warp owns 16 query rows. 64-key tiles.
// Epilogue writes ctx DIRECTLY into fragment-major afrag (no gmem round-trip).
// dyn smem: Ks 64x68 | Vs 64x72 | Ps 8x16x36  = 13568 floats = 54,272 B
#define ATTN_SMEM_FLOATS 13568
#define ATTN_SMEM_BYTES  (ATTN_SMEM_FLOATS * 4)
#define KS_OFF 0
#define VS_OFF 4352
#define PS_OFF 8960

__global__ void __launch_bounds__(256)
attn_mma_kernel(const float* __restrict__ Q, const float* __restrict__ K,
                const float* __restrict__ V, float* __restrict__ afrag)
{
    extern __shared__ float sm[];
    float* Ksm = sm + KS_OFF;   // [64][68]
    float* Vsm = sm + VS_OFF;   // [64][72]
    float* Psm = sm + PS_OFF;   // [8][16][36]

    const int b  = blockIdx.z;
    const int h  = blockIdx.y;
    const int qb = blockIdx.x * 128;
    const int tid = threadIdx.x;
    const int w    = tid >> 5;
    const int lane = tid & 31;
    const int g    = lane >> 2;
    const int tg   = lane & 3;
    const size_t base = (size_t)(b * SS) * DD + (size_t)h * HD;

    float qf[8][4];
    {
        const int r0 = qb + w * 16 + g;
        const int r1 = r0 + 8;
#pragma unroll
        for (int k8 = 0; k8 < 8; k8++) {
            int k0 = k8 * 8;
            qf[k8][0] = tf32r(Q[base + (size_t)r0 * DD + k0 + tg]     * 0.125f);
            qf[k8][1] = tf32r(Q[base + (size_t)r1 * DD + k0 + tg]     * 0.125f);
            qf[k8][2] = tf32r(Q[base + (size_t)r0 * DD + k0 + tg + 4] * 0.125f);
            qf[k8][3] = tf32r(Q[base + (size_t)r1 * DD + k0 + tg + 4] * 0.125f);
        }
    }

    float oacc[8][4];
#pragma unroll
    for (int nf = 0; nf < 8; nf++)
#pragma unroll
        for (int r = 0; r < 4; r++) oacc[nf][r] = 0.0f;
    float m0 = -1e30f, m1 = -1e30f, l0 = 0.0f, l1 = 0.0f;

    const int qmax_w = qb + w * 16 + 15;
    const int kend = qb + 128;
    float* Pw = Psm + w * 576;    // this warp's P buffer [16][36]

    for (int kt = 0; kt < kend; kt += 64) {
        // cooperative K/V tile load: 64x64 each, 1024 float4 over 256 threads
#pragma unroll
        for (int i = 0; i < 4; i++) {
            int idx4 = tid + i * 256;
            int r = idx4 >> 4;
            int c = (idx4 & 15) * 4;
            size_t ga = base + (size_t)(kt + r) * DD + c;
            float4 kv = *(const float4*)(K + ga);
            float4 vv = *(const float4*)(V + ga);
            float* kr = Ksm + r * 68 + c;
            float* vr = Vsm + r * 72 + c;
            kr[0] = tf32r(kv.x); kr[1] = tf32r(kv.y); kr[2] = tf32r(kv.z); kr[3] = tf32r(kv.w);
            vr[0] = tf32r(vv.x); vr[1] = tf32r(vv.y); vr[2] = tf32r(vv.z); vr[3] = tf32r(vv.w);
        }
        __syncthreads();

        if (kt <= qmax_w) {   // warp-uniform skip of fully-masked tiles
            // ---- S = Q.K^T over 64 keys ----
            float sacc[8][4];
#pragma unroll
            for (int nf = 0; nf < 8; nf++)
#pragma unroll
                for (int r = 0; r < 4; r++) sacc[nf][r] = 0.0f;
#pragma unroll
            for (int k8 = 0; k8 < 8; k8++) {
#pragma unroll
                for (int nf = 0; nf < 8; nf++) {
                    float bx = Ksm[(nf * 8 + g) * 68 + k8 * 8 + tg];
                    float by = Ksm[(nf * 8 + g) * 68 + k8 * 8 + tg + 4];
                    mma16n8k8(sacc[nf], qf[k8], bx, by);
                }
            }

            // ---- mask + online softmax (once per 64 keys) ----
            const int row0 = qb + w * 16 + g;
            const int row1 = row0 + 8;
#pragma unroll
            for (int nf = 0; nf < 8; nf++) {
#pragma unroll
                for (int e = 0; e < 2; e++) {
                    int key = kt + nf * 8 + tg * 2 + e;
                    if (key > row0) sacc[nf][e]     = -1e30f;
                    if (key > row1) sacc[nf][2 + e] = -1e30f;
                }
            }
            float t0 = -1e30f, t1 = -1e30f;
#pragma unroll
            for (int nf = 0; nf < 8; nf++) {
                t0 = fmaxf(t0, fmaxf(sacc[nf][0], sacc[nf][1]));
                t1 = fmaxf(t1, fmaxf(sacc[nf][2], sacc[nf][3]));
            }
            t0 = fmaxf(t0, __shfl_xor_sync(0xFFFFFFFFu, t0, 1));
            t0 = fmaxf(t0, __shfl_xor_sync(0xFFFFFFFFu, t0, 2));
            t1 = fmaxf(t1, __shfl_xor_sync(0xFFFFFFFFu, t1, 1));
            t1 = fmaxf(t1, __shfl_xor_sync(0xFFFFFFFFu, t1, 2));
            float nm0 = fmaxf(m0, t0);
            float nm1 = fmaxf(m1, t1);
            float c0 = __expf(m0 - nm0);
            float c1 = __expf(m1 - nm1);
            m0 = nm0; m1 = nm1;

            float ps0 = 0.0f, ps1 = 0.0f;
#pragma unroll
            for (int nf = 0; nf < 8; nf++) {
#pragma unroll
                for (int e = 0; e < 2; e++) {
                    float p0 = __expf(sacc[nf][e]     - nm0);
                    float p1 = __expf(sacc[nf][2 + e] - nm1);
                    sacc[nf][e]     = p0;
                    sacc[nf][2 + e] = p1;
                    ps0 += p0; ps1 += p1;
                }
            }
            ps0 += __shfl_xor_sync(0xFFFFFFFFu, ps0, 1);
            ps0 += __shfl_xor_sync(0xFFFFFFFFu, ps0, 2);
            ps1 += __shfl_xor_sync(0xFFFFFFFFu, ps1, 1);
            ps1 += __shfl_xor_sync(0xFFFFFFFFu, ps1, 2);
            l0 = l0 * c0 + ps0;
            l1 = l1 * c1 + ps1;

#pragma unroll
            for (int nf2 = 0; nf2 < 8; nf2++) {
                oacc[nf2][0] *= c0; oacc[nf2][1] *= c0;
                oacc[nf2][2] *= c1; oacc[nf2][3] *= c1;
            }

            // ---- PV phase A: P cols 0..31 (nf 0..3), V rows 0..31 ----
#pragma unroll
            for (int nf = 0; nf < 4; nf++) {
                float2 lo = make_float2(tf32r(sacc[nf][0]), tf32r(sacc[nf][1]));
                float2 hi = make_float2(tf32r(sacc[nf][2]), tf32r(sacc[nf][3]));
                *(float2*)&Pw[g * 36 + nf * 8 + tg * 2]       = lo;
                *(float2*)&Pw[(g + 8) * 36 + nf * 8 + tg * 2] = hi;
            }
            __syncwarp();
#pragma unroll
            for (int kk = 0; kk < 4; kk++) {
                float af[4];
                af[0] = Pw[g * 36 + kk * 8 + tg];
                af[1] = Pw[(g + 8) * 36 + kk * 8 + tg];
                af[2] = Pw[g * 36 + kk * 8 + tg + 4];
                af[3] = Pw[(g + 8) * 36 + kk * 8 + tg + 4];
#pragma unroll
                for (int nf2 = 0; nf2 < 8; nf2++) {
                    float bx = Vsm[(kk * 8 + tg) * 72 + nf2 * 8 + g];
                    float by = Vsm[(kk * 8 + tg + 4) * 72 + nf2 * 8 + g];
                    mma16n8k8(oacc[nf2], af, bx, by);
                }
            }
            __syncwarp();

            // ---- PV phase B: P cols 32..63 (nf 4..7), V rows 32..63 ----
#pragma unroll
            for (int nf = 4; nf < 8; nf++) {
                float2 lo = make_float2(tf32r(sacc[nf][0]), tf32r(sacc[nf][1]));
                float2 hi = make_float2(tf32r(sacc[nf][2]), tf32r(sacc[nf][3]));
                *(float2*)&Pw[g * 36 + (nf - 4) * 8 + tg * 2]       = lo;
                *(float2*)&Pw[(g + 8) * 36 + (nf - 4) * 8 + tg * 2] = hi;
            }
            __syncwarp();
#pragma unroll
            for (int kk = 0; kk < 4; kk++) {
                float af[4];
                af[0] = Pw[g * 36 + kk * 8 + tg];
                af[1] = Pw[(g + 8) * 36 + kk * 8 + tg];
                af[2] = Pw[g * 36 + kk * 8 + tg + 4];
                af[3] = Pw[(g + 8) * 36 + kk * 8 + tg + 4];
#pragma unroll
                for (int nf2 = 0; nf2 < 8; nf2++) {
                    float bx = Vsm[(32 + kk * 8 + tg) * 72 + nf2 * 8 + g];
                    float by = Vsm[(32 + kk * 8 + tg + 4) * 72 + nf2 * 8 + g];
                    mma16n8k8(oacc[nf2], af, bx, by);
                }
            }
        }
        __syncthreads();
    }

    // ---- epilogue: normalize + scatter into fragment-major afrag ----
    {
        const int row0 = b * SS + qb + w * 16 + g;   // global model row
        const int row1 = row0 + 8;
        const float inv0 = 1.0f / l0;
        const float inv1 = 1.0f / l1;
#pragma unroll
        for (int nf2 = 0; nf2 < 8; nf2++) {
            const int col = h * HD + nf2 * 8 + tg * 2;   // global feature col
            scatterA1(afrag, row0, col,     tf32r(oacc[nf2][0] * inv0));
            scatterA1(afrag, row0, col + 1, tf32r(oacc[nf2][1] * inv0));
            scatterA1(afrag, row1, col,     tf32r(oacc[nf2][2] * inv1));
            scatterA1(afrag, row1, col + 1, tf32r(oacc[nf2][3] * inv1));
        }
    }
}

// ------- residual add + layernorm; also emits fragment-major x -------------
__global__ void __launch_bounds__(256)
ln_res_kernel(float* __restrict__ x, const float* __restrict__ res,
              const float* __restrict__ g, const float* __restrict__ beta,
              float* __restrict__ afrag)
{
    __shared__ float red[256];
    const int row = blockIdx.x;
    const int tid = threadIdx.x;
    const int d0  = tid * 4;
    float* xr = x + (size_t)row * DD;
    const float* rr = res + (size_t)row * DD;

    float y[4];
    float s = 0.0f;
    {
        float4 xv = *(const float4*)(xr + d0);
        float4 rv = *(const float4*)(rr + d0);
        y[0] = xv.x + rv.x; y[1] = xv.y + rv.y;
        y[2] = xv.z + rv.z; y[3] = xv.w + rv.w;
        s = y[0] + y[1] + y[2] + y[3];
    }
    red[tid] = s; __syncthreads();
    for (int off = 128; off > 0; off >>= 1) {
        if (tid < off) red[tid] += red[tid + off];
        __syncthreads();
    }
    float mu = red[0] * (1.0f / (float)DD);
    __syncthreads();

    float vs = 0.0f;
#pragma unroll
    for (int i = 0; i < 4; i++) {
        float d2 = y[i] - mu;
        vs += d2 * d2;
    }
    red[tid] = vs; __syncthreads();
    for (int off = 128; off > 0; off >>= 1) {
        if (tid < off) red[tid] += red[tid + off];
        __syncthreads();
    }
    float var = red[0] * (1.0f / (float)DD);
    float inv = rsqrtf(var + 1e-5f);

    float out[4];
#pragma unroll
    for (int i = 0; i < 4; i++)
        out[i] = (y[i] - mu) * inv * g[d0 + i] + beta[d0 + i];
    *(float4*)(xr + d0) = *(float4*)out;
    float tv[4] = {tf32r(out[0]), tf32r(out[1]), tf32r(out[2]), tf32r(out[3])};
    scatterA(afrag, row, d0 >> 5, (d0 & 31) >> 2, tv);
}

// ---------------------------------------------------------------------------
extern "C" void kernel_launch(void* const* d_in, const int* in_sizes, int n_in,
                              void* d_out, int out_size)
{
    const int*   tokens = (const int*)  d_in[0];
    const float* emb    = (const float*)d_in[1];
    const float* qw     = (const float*)d_in[2];
    const float* qb     = (const float*)d_in[3];
    const float* kw     = (const float*)d_in[4];
    const float* kb     = (const float*)d_in[5];
    const float* vw     = (const float*)d_in[6];
    const float* vb     = (const float*)d_in[7];
    const float* ow     = (const float*)d_in[8];
    const float* ob     = (const float*)d_in[9];
    const float* ln_g   = (const float*)d_in[10];
    const float* ln_b   = (const float*)d_in[11];
    const float* out_w  = (const float*)d_in[12];
    const float* out_b  = (const float*)d_in[13];
    float* logits = (float*)d_out;

    float *x, *q, *k, *v, *attn, *afrag, *wfrag, *lwf;
    cudaGetSymbolAddress((void**)&x,     g_x);
    cudaGetSymbolAddress((void**)&q,     g_q);
    cudaGetSymbolAddress((void**)&k,     g_k);
    cudaGetSymbolAddress((void**)&v,     g_v);
    cudaGetSymbolAddress((void**)&attn,  g_attn);
    cudaGetSymbolAddress((void**)&afrag, g_afrag);
    cudaGetSymbolAddress((void**)&wfrag, g_wfrag);
    cudaGetSymbolAddress((void**)&lwf,   g_lwf);

    cudaFuncSetAttribute(gemm_pre,        cudaFuncAttributeMaxDynamicSharedMemorySize, GEMM_PRE_SMEM_BYTES);
    cudaFuncSetAttribute(gemm_pre_qkv,    cudaFuncAttributeMaxDynamicSharedMemorySize, GEMM_PRE_SMEM_BYTES);
    cudaFuncSetAttribute(attn_mma_kernel, cudaFuncAttributeMaxDynamicSharedMemorySize, ATTN_SMEM_BYTES);

    const size_t WMAT = (size_t)NT_D * KC_D * 4096;

    // weight prelayouts: logits (one launch) + ALL 16 layer mats (one launch)
    {
        dim3 gw(KC_D, NT_OUT);
        prelayout_W<<<gw, 256>>>(out_w, wfrag, VV);
        dim3 gall(KC_D, NT_D, LL * 4);
        prelayout_W_all<<<gall, 256>>>(qw, kw, vw, ow, lwf);
    }

    // embed writes x AND fragment-major afrag
    embed_kernel<<<NROW, 256>>>(tokens, emb, x, afrag);

    dim3 gqkv(MT_A, NT_D, 3);             // (16, 8, 3)
    dim3 gproj(MT_A, NT_D);               // (16, 8)
    dim3 gattn(SS / 128, HH, BB);         // (8, 16, 2)

    for (int l = 0; l < LL; l++) {
        size_t bo = (size_t)l * DD;
        gemm_pre_qkv<<<gqkv, 256, GEMM_PRE_SMEM_BYTES>>>(
            afrag,
            lwf + (size_t)(l * 4 + 0) * WMAT,
            lwf + (size_t)(l * 4 + 1) * WMAT,
            lwf + (size_t)(l * 4 + 2) * WMAT,
            qb + bo, kb + bo, vb + bo, q, k, v);
        // attention writes ctx directly into fragment-major afrag
        attn_mma_kernel<<<gattn, 256, ATTN_SMEM_BYTES>>>(q, k, v, afrag);
        gemm_pre<<<gproj, 256, GEMM_PRE_SMEM_BYTES>>>(
            afrag, lwf + (size_t)(l * 4 + 3) * WMAT, ob + bo, attn, DD, KC_D);
        ln_res_kernel<<<NROW, 256>>>(x, attn, ln_g + bo, ln_b + bo, afrag);
    }

    // final logits: afrag holds fragment-major x from last ln
    dim3 gout(MT_A, NT_OUT);              // (16, 250)
    gemm_pre<<<gout, 256, GEMM_PRE_SMEM_BYTES>>>(afrag, wfrag, out_b, logits, VV, KC_D);
}

// round 16
// speedup vs baseline: 1.2482x; 1.1894x over previous
#include <cuda_runtime.h>
#include <cuda_fp16.h>
#include <cstdint>
#include <math.h>

#define BB 2
#define SS 1024
#define DD 1024
#define HH 16
#define HD 64
#define LL 4
#define VV 32000
#define NROW (BB * SS)      // 2048
#define NT_OUT (VV / 128)   // 250
#define NT_D   (DD / 128)   // 8
#define MT_A   (NROW / 128) // 16
#define KC_D   (DD / 32)    // 32
// fp16 chunk: 128x32 (A) or 32x128 (B) halves = 4096 halves = 8 KB

// ---------------- scratch (static device globals; no allocs allowed) --------
__device__ float g_x[NROW * DD];
__device__ float g_q[NROW * DD];
__device__ float g_k[NROW * DD];
__device__ float g_v[NROW * DD];
__device__ float g_attn[NROW * DD];
__device__ __half g_afrag[(size_t)MT_A * KC_D * 4096];              // 4 MB
__device__ __half g_wfrag[(size_t)NT_OUT * KC_D * 4096];            // 65 MB
__device__ __half g_lwf[(size_t)LL * 4 * NT_D * KC_D * 4096];       // 32 MB

__device__ __forceinline__ float tf32r(float x) {
    float r; asm("cvt.rna.tf32.f32 %0, %1;" : "=f"(r) : "f"(x)); return r;
}

// tf32 m16n8k8 (attention only)
__device__ __forceinline__ void mma16n8k8(float* d, const float* a, float bx, float by) {
    asm volatile(
        "mma.sync.aligned.m16n8k8.row.col.f32.tf32.tf32.f32 "
        "{%0,%1,%2,%3}, {%4,%5,%6,%7}, {%8,%9}, {%0,%1,%2,%3};"
        : "+f"(d[0]), "+f"(d[1]), "+f"(d[2]), "+f"(d[3])
        : "r"(__float_as_uint(a[0])), "r"(__float_as_uint(a[1])),
          "r"(__float_as_uint(a[2])), "r"(__float_as_uint(a[3])),
          "r"(__float_as_uint(bx)), "r"(__float_as_uint(by)));
}

// fp16 m16n8k16, fp32 accumulate (GEMM path)
__device__ __forceinline__ void mmaf16(float* d, uint32_t a0, uint32_t a1,
                                       uint32_t a2, uint32_t a3,
                                       uint32_t b0, uint32_t b1) {
    asm volatile(
        "mma.sync.aligned.m16n8k16.row.col.f32.f16.f16.f32 "
        "{%0,%1,%2,%3}, {%4,%5,%6,%7}, {%8,%9}, {%0,%1,%2,%3};"
        : "+f"(d[0]), "+f"(d[1]), "+f"(d[2]), "+f"(d[3])
        : "r"(a0), "r"(a1), "r"(a2), "r"(a3), "r"(b0), "r"(b1));
}

__device__ __forceinline__ uint32_t smem_u32(const void* p) {
    uint32_t a;
    asm("{ .reg .u64 t; cvta.to.shared.u64 t, %1; cvt.u32.u64 %0, t; }" : "=r"(a) : "l"(p));
    return a;
}
__device__ __forceinline__ void cpasync16(uint32_t dst, const void* src) {
    asm volatile("cp.async.cg.shared.global [%0], [%1], 16;" :: "r"(dst), "l"(src));
}
#define CP_COMMIT() asm volatile("cp.async.commit_group;" ::: "memory")
#define CP_WAIT(n)  asm volatile("cp.async.wait_group %0;" :: "n"(n) : "memory")

// ---- fp16 fragment-major scatter: one half2 at (row, col even) -------------
// A chunk layout (u32 units): (mi*2+ki)*128 + lane*4 + r,  r=(m16>>3)+2*(k16>>3)
__device__ __forceinline__ void scatterA_pair(__half* __restrict__ afrag, int row,
                                              int col, __half2 h2)
{
    int mt = row >> 7, r127 = row & 127;
    int mi = r127 >> 4, m16 = r127 & 15;
    int g0 = m16 & 7, rh = m16 >> 3;
    int kc = col >> 5, c = col & 31;
    int ki = c >> 4, kk = c & 15;          // kk even
    int tg = (kk & 7) >> 1, khi = kk >> 3;
    int r  = rh + 2 * khi;
    int lane = g0 * 4 + tg;
    __half2* chunk = (__half2*)(afrag + ((size_t)mt * KC_D + kc) * 4096);
    chunk[(mi * 2 + ki) * 128 + lane * 4 + r] = h2;
}

// =================== weight prelayout (fp16 fragment-major) =================
// B chunk layout (u32 units): (ni*2+ki)*64 + lane*2 + hi,  hi=k16>>3
__device__ __forceinline__ void prelayout_W_body(
    const float* __restrict__ W, __half* __restrict__ dst, int N, int kc, int nt)
{
    const int t = threadIdx.x;
#pragma unroll
    for (int i = 0; i < 4; i++) {
        int idx = t + i * 256;                 // 0..1023 float4s
        int rowk = idx >> 5, c4 = idx & 31;
        int n0 = c4 * 4;
        int ki = rowk >> 4, kk = rowk & 15;
        int tg = (kk & 7) >> 1, hi = kk >> 3, hx = kk & 1;
        float4 v = *(const float4*)(W + (size_t)(kc * 32 + rowk) * N + nt * 128 + n0);
        float vv[4] = {v.x, v.y, v.z, v.w};
#pragma unroll
        for (int e = 0; e < 4; e++) {
            int n = n0 + e;
            int ni = n >> 3, g0 = n & 7;
            int lane = g0 * 4 + tg;
            int off = ((ni * 2 + ki) * 64 + lane * 2 + hi) * 2 + hx;
            dst[off] = __float2half_rn(vv[e]);
        }
    }
}

__global__ void __launch_bounds__(256)
prelayout_W(const float* __restrict__ W, __half* __restrict__ out, int N)
{
    __half* dst = out + ((size_t)blockIdx.y * gridDim.x + blockIdx.x) * 4096;
    prelayout_W_body(W, dst, N, blockIdx.x, blockIdx.y);
}

__global__ void __launch_bounds__(256)
prelayout_W_all(const float* __restrict__ qw, const float* __restrict__ kw,
                const float* __restrict__ vw, const float* __restrict__ ow,
                __half* __restrict__ out)
{
    const int z = blockIdx.z;
    const int l = z >> 2, m = z & 3;
    const float* base = (m == 0) ? qw : (m == 1) ? kw : (m == 2) ? vw : ow;
    const float* W = base + (size_t)l * DD * DD;
    __half* dst = out + ((size_t)z * NT_D * KC_D
                         + (size_t)blockIdx.y * KC_D + blockIdx.x) * 4096;
    prelayout_W_body(W, dst, DD, blockIdx.x, blockIdx.y);
}

// ============== fp16 GEMM on prelaid operands, cp.async 3-stage ring ========
#define PSTAGES 3
#define STAGE_BYTES 16384                       // A 8KB + B 8KB
#define GEMM_PRE_SMEM_BYTES (PSTAGES * STAGE_BYTES)   // 48 KB

__device__ __forceinline__ void gemm_pre_core(
    const __half* __restrict__ aSrc, const __half* __restrict__ bSrc,
    const float* __restrict__ bias, float* __restrict__ C,
    int N, int nkc, int mt, int nt, char* smc)
{
    const int t    = threadIdx.x;
    const int lane = t & 31;
    const int wid  = t >> 5;
    const int g    = lane >> 2;
    const int tg   = lane & 3;
    const int wm   = (wid & 1) * 64;
    const int wn   = (wid >> 1) * 32;
    const uint32_t smb = smem_u32(smc);

    float acc[4][4][4];
#pragma unroll
    for (int mf = 0; mf < 4; mf++)
#pragma unroll
        for (int nf = 0; nf < 4; nf++)
#pragma unroll
            for (int r = 0; r < 4; r++) acc[mf][nf][r] = 0.0f;

    auto issue = [&](int c) {
        uint32_t dstA = smb + (uint32_t)((c % PSTAGES) * STAGE_BYTES);
        uint32_t dstB = dstA + 8192u;
        const uint4* sa = (const uint4*)(aSrc + (size_t)c * 4096);
        const uint4* sb = (const uint4*)(bSrc + (size_t)c * 4096);
#pragma unroll
        for (int i = 0; i < 2; i++) {
            int o = t + i * 256;               // 0..511 uint4s
            cpasync16(dstA + (uint32_t)o * 16u, sa + o);
            cpasync16(dstB + (uint32_t)o * 16u, sb + o);
        }
        CP_COMMIT();
    };

    issue(0);
    issue(1);

    for (int kt = 0; kt < nkc; kt++) {
        if (kt + 1 < nkc) { CP_WAIT(1); } else { CP_WAIT(0); }
        __syncthreads();
        if (kt + 2 < nkc) issue(kt + 2);

        const uint32_t* asb = (const uint32_t*)(smc + (kt % PSTAGES) * STAGE_BYTES);
        const uint32_t* bsb = asb + 2048;
#pragma unroll
        for (int ki = 0; ki < 2; ki++) {
            uint4 afv[4];
            uint2 bfv[4];
#pragma unroll
            for (int mf = 0; mf < 4; mf++) {
                int mi = (wid & 1) * 4 + mf;
                afv[mf] = *(const uint4*)(asb + (mi * 2 + ki) * 128 + lane * 4);
            }
#pragma unroll
            for (int nf = 0; nf < 4; nf++) {
                int ni = (wid >> 1) * 4 + nf;
                bfv[nf] = *(const uint2*)(bsb + (ni * 2 + ki) * 64 + lane * 2);
            }
#pragma unroll
            for (int mf = 0; mf < 4; mf++)
#pragma unroll
                for (int nf = 0; nf < 4; nf++)
                    mmaf16(acc[mf][nf], afv[mf].x, afv[mf].y, afv[mf].z, afv[mf].w,
                           bfv[nf].x, bfv[nf].y);
        }
    }

#pragma unroll
    for (int mf = 0; mf < 4; mf++) {
        const int r0 = mt * 128 + wm + mf * 16 + g;
        const int r1 = r0 + 8;
#pragma unroll
        for (int nf = 0; nf < 4; nf++) {
            const int col = nt * 128 + wn + nf * 8 + tg * 2;
            const float b0 = bias[col], b1 = bias[col + 1];
            float2 v0 = make_float2(acc[mf][nf][0] + b0, acc[mf][nf][1] + b1);
            float2 v1 = make_float2(acc[mf][nf][2] + b0, acc[mf][nf][3] + b1);
            *(float2*)(C + (size_t)r0 * N + col) = v0;
            *(float2*)(C + (size_t)r1 * N + col) = v1;
        }
    }
}

__global__ void __launch_bounds__(256, 2)
gemm_pre(const __half* __restrict__ afrag, const __half* __restrict__ wfrag,
         const float* __restrict__ bias, float* __restrict__ C,
         int N, int nkc)
{
    extern __shared__ char smc[];
    const int mt = blockIdx.x, nt = blockIdx.y;
    gemm_pre_core(afrag + (size_t)mt * nkc * 4096,
                  wfrag + (size_t)nt * nkc * 4096,
                  bias, C, N, nkc, mt, nt, smc);
}

__global__ void __launch_bounds__(256, 2)
gemm_pre_qkv(const __half* __restrict__ afrag,
             const __half* __restrict__ qwf, const __half* __restrict__ kwf,
             const __half* __restrict__ vwf,
             const float* __restrict__ qb, const float* __restrict__ kb,
             const float* __restrict__ vb,
             float* __restrict__ qo, float* __restrict__ ko, float* __restrict__ vo)
{
    extern __shared__ char smc[];
    const int mt = blockIdx.x, nt = blockIdx.y;
    const __half* wf  = (blockIdx.z == 0) ? qwf : (blockIdx.z == 1) ? kwf : vwf;
    const float* bias = (blockIdx.z == 0) ? qb  : (blockIdx.z == 1) ? kb  : vb;
    float*       C    = (blockIdx.z == 0) ? qo  : (blockIdx.z == 1) ? ko  : vo;
    gemm_pre_core(afrag + (size_t)mt * KC_D * 4096,
                  wf    + (size_t)nt * KC_D * 4096,
                  bias, C, DD, KC_D, mt, nt, smc);
}

// -------- embedding + positional encoding; also emits fragment-major x -----
__global__ void __launch_bounds__(256)
embed_kernel(const int* __restrict__ tokens, const float* __restrict__ emb,
             float* __restrict__ x, __half* __restrict__ afrag)
{
    int row = blockIdx.x;
    int pos = row & (SS - 1);
    int tok = tokens[row];
    const float* e = emb + (size_t)tok * DD;
    float* xr = x + (size_t)row * DD;
    const float c = -logf(10000.0f) / (float)DD;
    const int d0 = threadIdx.x * 4;
    float vv[4];
#pragma unroll
    for (int j = 0; j < 4; j++) {
        int d = d0 + j;
        int i = d >> 1;
        float ang = (float)pos * expf((float)(2 * i) * c);
        float pe = (d & 1) ? cosf(ang) : sinf(ang);
        vv[j] = e[d] + pe;
    }
    *(float4*)(xr + d0) = *(float4*)vv;
    scatterA_pair(afrag, row, d0,     __floats2half2_rn(vv[0], vv[1]));
    scatterA_pair(afrag, row, d0 + 2, __floats2half2_rn(vv[2], vv[3]));
}

// ============= tensor-core causal flash attention (tf32 mma) ================
// 256 threads = 8 warps; warp owns 16 query rows. 64-key tiles.
// Epilogue writes ctx directly into fp16 fragment-major afrag.
#define ATTN_SMEM_FLOATS 13568
#define ATTN_SMEM_BYTES  (ATTN_SMEM_FLOATS * 4)
#define KS_OFF 0
#define VS_OFF 4352
#define PS_OFF 8960

__global__ void __launch_bounds__(256)
attn_mma_kernel(const float* __restrict__ Q, const float* __restrict__ K,
                const float* __restrict__ V, __half* __restrict__ afrag)
{
    extern __shared__ float sm[];
    float* Ksm = sm + KS_OFF;   // [64][68]
    float* Vsm = sm + VS_OFF;   // [64][72]
    float* Psm = sm + PS_OFF;   // [8][16][36]

    const int b  = blockIdx.z;
    const int h  = blockIdx.y;
    const int qb = blockIdx.x * 128;
    const int tid = threadIdx.x;
    const int w    = tid >> 5;
    const int lane = tid & 31;
    const int g    = lane >> 2;
    const int tg   = lane & 3;
    const size_t base = (size_t)(b * SS) * DD + (size_t)h * HD;

    float qf[8][4];
    {
        const int r0 = qb + w * 16 + g;
        const int r1 = r0 + 8;
#pragma unroll
        for (int k8 = 0; k8 < 8; k8++) {
            int k0 = k8 * 8;
            qf[k8][0] = tf32r(Q[base + (size_t)r0 * DD + k0 + tg]     * 0.125f);
            qf[k8][1] = tf32r(Q[base + (size_t)r1 * DD + k0 + tg]     * 0.125f);
            qf[k8][2] = tf32r(Q[base + (size_t)r0 * DD + k0 + tg + 4] * 0.125f);
            qf[k8][3] = tf32r(Q[base + (size_t)r1 * DD + k0 + tg + 4] * 0.125f);
        }
    }

    float oacc[8][4];
#pragma unroll
    for (int nf = 0; nf < 8; nf++)
#pragma unroll
        for (int r = 0; r < 4; r++) oacc[nf][r] = 0.0f;
    float m0 = -1e30f, m1 = -1e30f, l0 = 0.0f, l1 = 0.0f;

    const int qmax_w = qb + w * 16 + 15;
    const int kend = qb + 128;
    float* Pw = Psm + w * 576;

    for (int kt = 0; kt < kend; kt += 64) {
#pragma unroll
        for (int i = 0; i < 4; i++) {
            int idx4 = tid + i * 256;
            int r = idx4 >> 4;
            int c = (idx4 & 15) * 4;
            size_t ga = base + (size_t)(kt + r) * DD + c;
            float4 kv = *(const float4*)(K + ga);
            float4 vv = *(const float4*)(V + ga);
            float* kr = Ksm + r * 68 + c;
            float* vr = Vsm + r * 72 + c;
            kr[0] = tf32r(kv.x); kr[1] = tf32r(kv.y); kr[2] = tf32r(kv.z); kr[3] = tf32r(kv.w);
            vr[0] = tf32r(vv.x); vr[1] = tf32r(vv.y); vr[2] = tf32r(vv.z); vr[3] = tf32r(vv.w);
        }
        __syncthreads();

        if (kt <= qmax_w) {
            float sacc[8][4];
#pragma unroll
            for (int nf = 0; nf < 8; nf++)
#pragma unroll
                for (int r = 0; r < 4; r++) sacc[nf][r] = 0.0f;
#pragma unroll
            for (int k8 = 0; k8 < 8; k8++) {
#pragma unroll
                for (int nf = 0; nf < 8; nf++) {
                    float bx = Ksm[(nf * 8 + g) * 68 + k8 * 8 + tg];
                    float by = Ksm[(nf * 8 + g) * 68 + k8 * 8 + tg + 4];
                    mma16n8k8(sacc[nf], qf[k8], bx, by);
                }
            }

            const int row0 = qb + w * 16 + g;
            const int row1 = row0 + 8;
#pragma unroll
            for (int nf = 0; nf < 8; nf++) {
#pragma unroll
                for (int e = 0; e < 2; e++) {
                    int key = kt + nf * 8 + tg * 2 + e;
                    if (key > row0) sacc[nf][e]     = -1e30f;
                    if (key > row1) sacc[nf][2 + e] = -1e30f;
                }
            }
            float t0 = -1e30f, t1 = -1e30f;
#pragma unroll
            for (int nf = 0; nf < 8; nf++) {
                t0 = fmaxf(t0, fmaxf(sacc[nf][0], sacc[nf][1]));
                t1 = fmaxf(t1, fmaxf(sacc[nf][2], sacc[nf][3]));
            }
            t0 = fmaxf(t0, __shfl_xor_sync(0xFFFFFFFFu, t0, 1));
            t0 = fmaxf(t0, __shfl_xor_sync(0xFFFFFFFFu, t0, 2));
            t1 = fmaxf(t1, __shfl_xor_sync(0xFFFFFFFFu, t1, 1));
            t1 = fmaxf(t1, __shfl_xor_sync(0xFFFFFFFFu, t1, 2));
            float nm0 = fmaxf(m0, t0);
            float nm1 = fmaxf(m1, t1);
            float c0 = __expf(m0 - nm0);
            float c1 = __expf(m1 - nm1);
            m0 = nm0; m1 = nm1;

            float ps0 = 0.0f, ps1 = 0.0f;
#pragma unroll
            for (int nf = 0; nf < 8; nf++) {
#pragma unroll
                for (int e = 0; e < 2; e++) {
                    float p0 = __expf(sacc[nf][e]     - nm0);
                    float p1 = __expf(sacc[nf][2 + e] - nm1);
                    sacc[nf][e]     = p0;
                    sacc[nf][2 + e] = p1;
                    ps0 += p0; ps1 += p1;
                }
            }
            ps0 += __shfl_xor_sync(0xFFFFFFFFu, ps0, 1);
            ps0 += __shfl_xor_sync(0xFFFFFFFFu, ps0, 2);
            ps1 += __shfl_xor_sync(0xFFFFFFFFu, ps1, 1);
            ps1 += __shfl_xor_sync(0xFFFFFFFFu, ps1, 2);
            l0 = l0 * c0 + ps0;
            l1 = l1 * c1 + ps1;

#pragma unroll
            for (int nf2 = 0; nf2 < 8; nf2++) {
                oacc[nf2][0] *= c0; oacc[nf2][1] *= c0;
                oacc[nf2][2] *= c1; oacc[nf2][3] *= c1;
            }

            // PV phase A: P cols 0..31, V rows 0..31
#pragma unroll
            for (int nf = 0; nf < 4; nf++) {
                float2 lo = make_float2(tf32r(sacc[nf][0]), tf32r(sacc[nf][1]));
                float2 hi = make_float2(tf32r(sacc[nf][2]), tf32r(sacc[nf][3]));
                *(float2*)&Pw[g * 36 + nf * 8 + tg * 2]       = lo;
                *(float2*)&Pw[(g + 8) * 36 + nf * 8 + tg * 2] = hi;
            }
            __syncwarp();
#pragma unroll
            for (int kk = 0; kk < 4; kk++) {
                float af[4];
                af[0] = Pw[g * 36 + kk * 8 + tg];
                af[1] = Pw[(g + 8) * 36 + kk * 8 + tg];
                af[2] = Pw[g * 36 + kk * 8 + tg + 4];
                af[3] = Pw[(g + 8) * 36 + kk * 8 + tg + 4];
#pragma unroll
                for (int nf2 = 0; nf2 < 8; nf2++) {
                    float bx = Vsm[(kk * 8 + tg) * 72 + nf2 * 8 + g];
                    float by = Vsm[(kk * 8 + tg + 4) * 72 + nf2 * 8 + g];
                    mma16n8k8(oacc[nf2], af, bx, by);
                }
            }
            __syncwarp();

            // PV phase B: P cols 32..63, V rows 32..63
#pragma unroll
            for (int nf = 4; nf < 8; nf++) {
                float2 lo = make_float2(tf32r(sacc[nf][0]), tf32r(sacc[nf][1]));
                float2 hi = make_float2(tf32r(sacc[nf][2]), tf32r(sacc[nf][3]));
                *(float2*)&Pw[g * 36 + (nf - 4) * 8 + tg * 2]       = lo;
                *(float2*)&Pw[(g + 8) * 36 + (nf - 4) * 8 + tg * 2] = hi;
            }
            __syncwarp();
#pragma unroll
            for (int kk = 0; kk < 4; kk++) {
                float af[4];
                af[0] = Pw[g * 36 + kk * 8 + tg];
                af[1] = Pw[(g + 8) * 36 + kk * 8 + tg];
                af[2] = Pw[g * 36 + kk * 8 + tg + 4];
                af[3] = Pw[(g + 8) * 36 + kk * 8 + tg + 4];
#pragma unroll
                for (int nf2 = 0; nf2 < 8; nf2++) {
                    float bx = Vsm[(32 + kk * 8 + tg) * 72 + nf2 * 8 + g];
                    float by = Vsm[(32 + kk * 8 + tg + 4) * 72 + nf2 * 8 + g];
                    mma16n8k8(oacc[nf2], af, bx, by);
                }
            }
        }
        __syncthreads();
    }

    // epilogue: normalize + fp16 fragment-major scatter
    {
        const int row0 = b * SS + qb + w * 16 + g;
        const int row1 = row0 + 8;
        const float inv0 = 1.0f / l0;
        const float inv1 = 1.0f / l1;
#pragma unroll
        for (int nf2 = 0; nf2 < 8; nf2++) {
            const int col = h * HD + nf2 * 8 + tg * 2;
            scatterA_pair(afrag, row0, col,
                          __floats2half2_rn(oacc[nf2][0] * inv0, oacc[nf2][1] * inv0));
            scatterA_pair(afrag, row1, col,
                          __floats2half2_rn(oacc[nf2][2] * inv1, oacc[nf2][3] * inv1));
        }
    }
}

// ------- residual add + layernorm; also emits fp16 fragment-major x --------
__global__ void __launch_bounds__(256)
ln_res_kernel(float* __restrict__ x, const float* __restrict__ res,
              const float* __restrict__ g, const float* __restrict__ beta,
              __half* __restrict__ afrag)
{
    __shared__ float red[256];
    const int row = blockIdx.x;
    const int tid = threadIdx.x;
    const int d0  = tid * 4;
    float* xr = x + (size_t)row * DD;
    const float* rr = res + (size_t)row * DD;

    float y[4];
    float s = 0.0f;
    {
        float4 xv = *(const float4*)(xr + d0);
        float4 rv = *(const float4*)(rr + d0);
        y[0] = xv.x + rv.x; y[1] = xv.y + rv.y;
        y[2] = xv.z + rv.z; y[3] = xv.w + rv.w;
        s = y[0] + y[1] + y[2] + y[3];
    }
    red[tid] = s; __syncthreads();
    for (int off = 128; off > 0; off >>= 1) {
        if (tid < off) red[tid] += red[tid + off];
        __syncthreads();
    }
    float mu = red[0] * (1.0f / (float)DD);
    __syncthreads();

    float vs = 0.0f;
#pragma unroll
    for (int i = 0; i < 4; i++) {
        float d2 = y[i] - mu;
        vs += d2 * d2;
    }
    red[tid] = vs; __syncthreads();
    for (int off = 128; off > 0; off >>= 1) {
        if (tid < off) red[tid] += red[tid + off];
        __syncthreads();
    }
    float var = red[0] * (1.0f / (float)DD);
    float inv = rsqrtf(var + 1e-5f);

    float out[4];
#pragma unroll
    for (int i = 0; i < 4; i++)
        out[i] = (y[i] - mu) * inv * g[d0 + i] + beta[d0 + i];
    *(float4*)(xr + d0) = *(float4*)out;
    scatterA_pair(afrag, row, d0,     __floats2half2_rn(out[0], out[1]));
    scatterA_pair(afrag, row, d0 + 2, __floats2half2_rn(out[2], out[3]));
}

// ---------------------------------------------------------------------------
extern "C" void kernel_launch(void* const* d_in, const int* in_sizes, int n_in,
                              void* d_out, int out_size)
{
    const int*   tokens = (const int*)  d_in[0];
    const float* emb    = (const float*)d_in[1];
    const float* qw     = (const float*)d_in[2];
    const float* qb     = (const float*)d_in[3];
    const float* kw     = (const float*)d_in[4];
    const float* kb     = (const float*)d_in[5];
    const float* vw     = (const float*)d_in[6];
    const float* vb     = (const float*)d_in[7];
    const float* ow     = (const float*)d_in[8];
    const float* ob     = (const float*)d_in[9];
    const float* ln_g   = (const float*)d_in[10];
    const float* ln_b   = (const float*)d_in[11];
    const float* out_w  = (const float*)d_in[12];
    const float* out_b  = (const float*)d_in[13];
    float* logits = (float*)d_out;

    float *x, *q, *k, *v, *attn;
    __half *afrag, *wfrag, *lwf;
    cudaGetSymbolAddress((void**)&x,     g_x);
    cudaGetSymbolAddress((void**)&q,     g_q);
    cudaGetSymbolAddress((void**)&k,     g_k);
    cudaGetSymbolAddress((void**)&v,     g_v);
    cudaGetSymbolAddress((void**)&attn,  g_attn);
    cudaGetSymbolAddress((void**)&afrag, g_afrag);
    cudaGetSymbolAddress((void**)&wfrag, g_wfrag);
    cudaGetSymbolAddress((void**)&lwf,   g_lwf);

    cudaFuncSetAttribute(gemm_pre,        cudaFuncAttributeMaxDynamicSharedMemorySize, GEMM_PRE_SMEM_BYTES);
    cudaFuncSetAttribute(gemm_pre_qkv,    cudaFuncAttributeMaxDynamicSharedMemorySize, GEMM_PRE_SMEM_BYTES);
    cudaFuncSetAttribute(attn_mma_kernel, cudaFuncAttributeMaxDynamicSharedMemorySize, ATTN_SMEM_BYTES);

    const size_t WMAT = (size_t)NT_D * KC_D * 4096;   // halves per layer matrix

    // weight prelayouts: logits (one launch) + ALL 16 layer mats (one launch)
    {
        dim3 gw(KC_D, NT_OUT);
        prelayout_W<<<gw, 256>>>(out_w, wfrag, VV);
        dim3 gall(KC_D, NT_D, LL * 4);
        prelayout_W_all<<<gall, 256>>>(qw, kw, vw, ow, lwf);
    }

    embed_kernel<<<NROW, 256>>>(tokens, emb, x, afrag);

    dim3 gqkv(MT_A, NT_D, 3);             // (16, 8, 3)
    dim3 gproj(MT_A, NT_D);               // (16, 8)
    dim3 gattn(SS / 128, HH, BB);         // (8, 16, 2)

    for (int l = 0; l < LL; l++) {
        size_t bo = (size_t)l * DD;
        gemm_pre_qkv<<<gqkv, 256, GEMM_PRE_SMEM_BYTES>>>(
            afrag,
            lwf + (size_t)(l * 4 + 0) * WMAT,
            lwf + (size_t)(l * 4 + 1) * WMAT,
            lwf + (size_t)(l * 4 + 2) * WMAT,
            qb + bo, kb + bo, vb + bo, q, k, v);
        attn_mma_kernel<<<gattn, 256, ATTN_SMEM_BYTES>>>(q, k, v, afrag);
        gemm_pre<<<gproj, 256, GEMM_PRE_SMEM_BYTES>>>(
            afrag, lwf + (size_t)(l * 4 + 3) * WMAT, ob + bo, attn, DD, KC_D);
        ln_res_kernel<<<NROW, 256>>>(x, attn, ln_g + bo, ln_b + bo, afrag);
    }

    // final logits
    dim3 gout(MT_A, NT_OUT);              // (16, 250)
    gemm_pre<<<gout, 256, GEMM_PRE_SMEM_BYTES>>>(afrag, wfrag, out_b, logits, VV, KC_D);
}

// round 17
// speedup vs baseline: 1.3280x; 1.0639x over previous
#include <cuda_runtime.h>
#include <cuda_fp16.h>
#include <cstdint>
#include <math.h>

#define BB 2
#define SS 1024
#define DD 1024
#define HH 16
#define HD 64
#define LL 4
#define VV 32000
#define NROW (BB * SS)      // 2048
#define NT_OUT (VV / 128)   // 250
#define NT_D   (DD / 128)   // 8
#define MT_A   (NROW / 128) // 16
#define KC2    (DD / 64)    // 16 K-chunks of 64
#define CHUNK_H 8192        // halves per chunk (128x64 A or 64x128 B)

// ---------------- scratch (static device globals; no allocs allowed) --------
__device__ float g_x[NROW * DD];
__device__ float g_q[NROW * DD];
__device__ float g_k[NROW * DD];
__device__ float g_v[NROW * DD];
__device__ float g_attn[NROW * DD];
__device__ __half g_afrag[(size_t)MT_A * KC2 * CHUNK_H];            // 4 MB
__device__ __half g_wfrag[(size_t)NT_OUT * KC2 * CHUNK_H];          // 65 MB
__device__ __half g_lwf[(size_t)LL * 4 * NT_D * KC2 * CHUNK_H];     // 32 MB

__device__ __forceinline__ float tf32r(float x) {
    float r; asm("cvt.rna.tf32.f32 %0, %1;" : "=f"(r) : "f"(x)); return r;
}

// tf32 m16n8k8 (attention only)
__device__ __forceinline__ void mma16n8k8(float* d, const float* a, float bx, float by) {
    asm volatile(
        "mma.sync.aligned.m16n8k8.row.col.f32.tf32.tf32.f32 "
        "{%0,%1,%2,%3}, {%4,%5,%6,%7}, {%8,%9}, {%0,%1,%2,%3};"
        : "+f"(d[0]), "+f"(d[1]), "+f"(d[2]), "+f"(d[3])
        : "r"(__float_as_uint(a[0])), "r"(__float_as_uint(a[1])),
          "r"(__float_as_uint(a[2])), "r"(__float_as_uint(a[3])),
          "r"(__float_as_uint(bx)), "r"(__float_as_uint(by)));
}

// fp16 m16n8k16, fp32 accumulate (GEMM path)
__device__ __forceinline__ void mmaf16(float* d, uint32_t a0, uint32_t a1,
                                       uint32_t a2, uint32_t a3,
                                       uint32_t b0, uint32_t b1) {
    asm volatile(
        "mma.sync.aligned.m16n8k16.row.col.f32.f16.f16.f32 "
        "{%0,%1,%2,%3}, {%4,%5,%6,%7}, {%8,%9}, {%0,%1,%2,%3};"
        : "+f"(d[0]), "+f"(d[1]), "+f"(d[2]), "+f"(d[3])
        : "r"(a0), "r"(a1), "r"(a2), "r"(a3), "r"(b0), "r"(b1));
}

__device__ __forceinline__ uint32_t smem_u32(const void* p) {
    uint32_t a;
    asm("{ .reg .u64 t; cvta.to.shared.u64 t, %1; cvt.u32.u64 %0, t; }" : "=r"(a) : "l"(p));
    return a;
}
__device__ __forceinline__ void cpasync16(uint32_t dst, const void* src) {
    asm volatile("cp.async.cg.shared.global [%0], [%1], 16;" :: "r"(dst), "l"(src));
}
#define CP_COMMIT() asm volatile("cp.async.commit_group;" ::: "memory")
#define CP_WAIT(n)  asm volatile("cp.async.wait_group %0;" :: "n"(n) : "memory")

// ---- fp16 fragment-major scatter: one half2 at (row, col even) -------------
// A chunk layout (u32 units): (mi*4+ki)*128 + lane*4 + r,  r=(m16>>3)+2*(k16>>3)
__device__ __forceinline__ void scatterA_pair(__half* __restrict__ afrag, int row,
                                              int col, __half2 h2)
{
    int mt = row >> 7, r127 = row & 127;
    int mi = r127 >> 4, m16 = r127 & 15;
    int g0 = m16 & 7, rh = m16 >> 3;
    int kc = col >> 6, c = col & 63;
    int ki = c >> 4, kk = c & 15;          // kk even
    int tg = (kk & 7) >> 1, khi = kk >> 3;
    int r  = rh + 2 * khi;
    int lane = g0 * 4 + tg;
    __half2* chunk = (__half2*)(afrag + ((size_t)mt * KC2 + kc) * CHUNK_H);
    chunk[(mi * 4 + ki) * 128 + lane * 4 + r] = h2;
}

// =================== weight prelayout (fp16 fragment-major) =================
// B chunk layout (u32 units): (ni*4+ki)*64 + lane*2 + hi,  hi=k16>>3
__device__ __forceinline__ void prelayout_W_body(
    const float* __restrict__ W, __half* __restrict__ dst, int N, int kc, int nt)
{
    const int t = threadIdx.x;
#pragma unroll
    for (int i = 0; i < 8; i++) {
        int idx = t + i * 256;                 // 0..2047 float4s (64 rows x 32 f4)
        int rowk = idx >> 5, c4 = idx & 31;
        int n0 = c4 * 4;
        int ki = rowk >> 4, kk = rowk & 15;
        int tg = (kk & 7) >> 1, hi = kk >> 3, hx = kk & 1;
        float4 v = *(const float4*)(W + (size_t)(kc * 64 + rowk) * N + nt * 128 + n0);
        float vv[4] = {v.x, v.y, v.z, v.w};
#pragma unroll
        for (int e = 0; e < 4; e++) {
            int n = n0 + e;
            int ni = n >> 3, g0 = n & 7;
            int lane = g0 * 4 + tg;
            int off = ((ni * 4 + ki) * 64 + lane * 2 + hi) * 2 + hx;
            dst[off] = __float2half_rn(vv[e]);
        }
    }
}

__global__ void __launch_bounds__(256)
prelayout_W(const float* __restrict__ W, __half* __restrict__ out, int N)
{
    __half* dst = out + ((size_t)blockIdx.y * gridDim.x + blockIdx.x) * CHUNK_H;
    prelayout_W_body(W, dst, N, blockIdx.x, blockIdx.y);
}

__global__ void __launch_bounds__(256)
prelayout_W_all(const float* __restrict__ qw, const float* __restrict__ kw,
                const float* __restrict__ vw, const float* __restrict__ ow,
                __half* __restrict__ out)
{
    const int z = blockIdx.z;
    const int l = z >> 2, m = z & 3;
    const float* base = (m == 0) ? qw : (m == 1) ? kw : (m == 2) ? vw : ow;
    const float* W = base + (size_t)l * DD * DD;
    __half* dst = out + ((size_t)z * NT_D * KC2
                         + (size_t)blockIdx.y * KC2 + blockIdx.x) * CHUNK_H;
    prelayout_W_body(W, dst, DD, blockIdx.x, blockIdx.y);
}

// ============== fp16 GEMM, K-chunk 64, cp.async 3-stage ring ================
#define PSTAGES 3
#define STAGE_BYTES 32768                       // A 16KB + B 16KB
#define GEMM_PRE_SMEM_BYTES (PSTAGES * STAGE_BYTES)   // 96 KB

__device__ __forceinline__ void gemm_pre_core(
    const __half* __restrict__ aSrc, const __half* __restrict__ bSrc,
    const float* __restrict__ bias, float* __restrict__ C,
    int N, int nkc, int mt, int nt, char* smc)
{
    const int t    = threadIdx.x;
    const int lane = t & 31;
    const int wid  = t >> 5;
    const int g    = lane >> 2;
    const int tg   = lane & 3;
    const int wm   = (wid & 1) * 64;
    const int wn   = (wid >> 1) * 32;
    const uint32_t smb = smem_u32(smc);

    float acc[4][4][4];
#pragma unroll
    for (int mf = 0; mf < 4; mf++)
#pragma unroll
        for (int nf = 0; nf < 4; nf++)
#pragma unroll
            for (int r = 0; r < 4; r++) acc[mf][nf][r] = 0.0f;

    auto issue = [&](int c) {
        uint32_t dstA = smb + (uint32_t)((c % PSTAGES) * STAGE_BYTES);
        uint32_t dstB = dstA + 16384u;
        const uint4* sa = (const uint4*)(aSrc + (size_t)c * CHUNK_H);
        const uint4* sb = (const uint4*)(bSrc + (size_t)c * CHUNK_H);
#pragma unroll
        for (int i = 0; i < 4; i++) {
            int o = t + i * 256;               // 0..1023 uint4s
            cpasync16(dstA + (uint32_t)o * 16u, sa + o);
            cpasync16(dstB + (uint32_t)o * 16u, sb + o);
        }
        CP_COMMIT();
    };

    issue(0);
    issue(1);

    for (int kt = 0; kt < nkc; kt++) {
        if (kt + 1 < nkc) { CP_WAIT(1); } else { CP_WAIT(0); }
        __syncthreads();
        if (kt + 2 < nkc) issue(kt + 2);

        const uint32_t* asb = (const uint32_t*)(smc + (kt % PSTAGES) * STAGE_BYTES);
        const uint32_t* bsb = asb + 4096;
#pragma unroll
        for (int ki = 0; ki < 4; ki++) {
            uint4 afv[4];
            uint2 bfv[4];
#pragma unroll
            for (int mf = 0; mf < 4; mf++) {
                int mi = (wid & 1) * 4 + mf;
                afv[mf] = *(const uint4*)(asb + (mi * 4 + ki) * 128 + lane * 4);
            }
#pragma unroll
            for (int nf = 0; nf < 4; nf++) {
                int ni = (wid >> 1) * 4 + nf;
                bfv[nf] = *(const uint2*)(bsb + (ni * 4 + ki) * 64 + lane * 2);
            }
#pragma unroll
            for (int mf = 0; mf < 4; mf++)
#pragma unroll
                for (int nf = 0; nf < 4; nf++)
                    mmaf16(acc[mf][nf], afv[mf].x, afv[mf].y, afv[mf].z, afv[mf].w,
                           bfv[nf].x, bfv[nf].y);
        }
    }

#pragma unroll
    for (int mf = 0; mf < 4; mf++) {
        const int r0 = mt * 128 + wm + mf * 16 + g;
        const int r1 = r0 + 8;
#pragma unroll
        for (int nf = 0; nf < 4; nf++) {
            const int col = nt * 128 + wn + nf * 8 + tg * 2;
            const float b0 = bias[col], b1 = bias[col + 1];
            float2 v0 = make_float2(acc[mf][nf][0] + b0, acc[mf][nf][1] + b1);
            float2 v1 = make_float2(acc[mf][nf][2] + b0, acc[mf][nf][3] + b1);
            *(float2*)(C + (size_t)r0 * N + col) = v0;
            *(float2*)(C + (size_t)r1 * N + col) = v1;
        }
    }
}

__global__ void __launch_bounds__(256, 2)
gemm_pre(const __half* __restrict__ afrag, const __half* __restrict__ wfrag,
         const float* __restrict__ bias, float* __restrict__ C,
         int N, int nkc)
{
    extern __shared__ char smc[];
    const int mt = blockIdx.x, nt = blockIdx.y;
    gemm_pre_core(afrag + (size_t)mt * nkc * CHUNK_H,
                  wfrag + (size_t)nt * nkc * CHUNK_H,
                  bias, C, N, nkc, mt, nt, smc);
}

__global__ void __launch_bounds__(256, 2)
gemm_pre_qkv(const __half* __restrict__ afrag,
             const __half* __restrict__ qwf, const __half* __restrict__ kwf,
             const __half* __restrict__ vwf,
             const float* __restrict__ qb, const float* __restrict__ kb,
             const float* __restrict__ vb,
             float* __restrict__ qo, float* __restrict__ ko, float* __restrict__ vo)
{
    extern __shared__ char smc[];
    const int mt = blockIdx.x, nt = blockIdx.y;
    const __half* wf  = (blockIdx.z == 0) ? qwf : (blockIdx.z == 1) ? kwf : vwf;
    const float* bias = (blockIdx.z == 0) ? qb  : (blockIdx.z == 1) ? kb  : vb;
    float*       C    = (blockIdx.z == 0) ? qo  : (blockIdx.z == 1) ? ko  : vo;
    gemm_pre_core(afrag + (size_t)mt * KC2 * CHUNK_H,
                  wf    + (size_t)nt * KC2 * CHUNK_H,
                  bias, C, DD, KC2, mt, nt, smc);
}

// -------- embedding + positional encoding; also emits fragment-major x -----
__global__ void __launch_bounds__(256)
embed_kernel(const int* __restrict__ tokens, const float* __restrict__ emb,
             float* __restrict__ x, __half* __restrict__ afrag)
{
    int row = blockIdx.x;
    int pos = row & (SS - 1);
    int tok = tokens[row];
    const float* e = emb + (size_t)tok * DD;
    float* xr = x + (size_t)row * DD;
    const float c = -logf(10000.0f) / (float)DD;
    const int d0 = threadIdx.x * 4;
    float vv[4];
#pragma unroll
    for (int j = 0; j < 4; j++) {
        int d = d0 + j;
        int i = d >> 1;
        float ang = (float)pos * expf((float)(2 * i) * c);
        float pe = (d & 1) ? cosf(ang) : sinf(ang);
        vv[j] = e[d] + pe;
    }
    *(float4*)(xr + d0) = *(float4*)vv;
    scatterA_pair(afrag, row, d0,     __floats2half2_rn(vv[0], vv[1]));
    scatterA_pair(afrag, row, d0 + 2, __floats2half2_rn(vv[2], vv[3]));
}

// ============= tensor-core causal flash attention (tf32 mma) ================
// 256 threads = 8 warps; warp owns 16 query rows. 64-key tiles.
#define ATTN_SMEM_FLOATS 13568
#define ATTN_SMEM_BYTES  (ATTN_SMEM_FLOATS * 4)
#define KS_OFF 0
#define VS_OFF 4352
#define PS_OFF 8960

__global__ void __launch_bounds__(256)
attn_mma_kernel(const float* __restrict__ Q, const float* __restrict__ K,
                const float* __restrict__ V, __half* __restrict__ afrag)
{
    extern __shared__ float sm[];
    float* Ksm = sm + KS_OFF;   // [64][68]
    float* Vsm = sm + VS_OFF;   // [64][72]
    float* Psm = sm + PS_OFF;   // [8][16][36]

    const int b  = blockIdx.z;
    const int h  = blockIdx.y;
    const int qb = blockIdx.x * 128;
    const int tid = threadIdx.x;
    const int w    = tid >> 5;
    const int lane = tid & 31;
    const int g    = lane >> 2;
    const int tg   = lane & 3;
    const size_t base = (size_t)(b * SS) * DD + (size_t)h * HD;

    float qf[8][4];
    {
        const int r0 = qb + w * 16 + g;
        const int r1 = r0 + 8;
#pragma unroll
        for (int k8 = 0; k8 < 8; k8++) {
            int k0 = k8 * 8;
            qf[k8][0] = tf32r(Q[base + (size_t)r0 * DD + k0 + tg]     * 0.125f);
            qf[k8][1] = tf32r(Q[base + (size_t)r1 * DD + k0 + tg]     * 0.125f);
            qf[k8][2] = tf32r(Q[base + (size_t)r0 * DD + k0 + tg + 4] * 0.125f);
            qf[k8][3] = tf32r(Q[base + (size_t)r1 * DD + k0 + tg + 4] * 0.125f);
        }
    }

    float oacc[8][4];
#pragma unroll
    for (int nf = 0; nf < 8; nf++)
#pragma unroll
        for (int r = 0; r < 4; r++) oacc[nf][r] = 0.0f;
    float m0 = -1e30f, m1 = -1e30f, l0 = 0.0f, l1 = 0.0f;

    const int qmax_w = qb + w * 16 + 15;
    const int kend = qb + 128;
    float* Pw = Psm + w * 576;

    for (int kt = 0; kt < kend; kt += 64) {
#pragma unroll
        for (int i = 0; i < 4; i++) {
            int idx4 = tid + i * 256;
            int r = idx4 >> 4;
            int c = (idx4 & 15) * 4;
            size_t ga = base + (size_t)(kt + r) * DD + c;
            float4 kv = *(const float4*)(K + ga);
            float4 vv = *(const float4*)(V + ga);
            float* kr = Ksm + r * 68 + c;
            float* vr = Vsm + r * 72 + c;
            kr[0] = tf32r(kv.x); kr[1] = tf32r(kv.y); kr[2] = tf32r(kv.z); kr[3] = tf32r(kv.w);
            vr[0] = tf32r(vv.x); vr[1] = tf32r(vv.y); vr[2] = tf32r(vv.z); vr[3] = tf32r(vv.w);
        }
        __syncthreads();

        if (kt <= qmax_w) {
            float sacc[8][4];
#pragma unroll
            for (int nf = 0; nf < 8; nf++)
#pragma unroll
                for (int r = 0; r < 4; r++) sacc[nf][r] = 0.0f;
#pragma unroll
            for (int k8 = 0; k8 < 8; k8++) {
#pragma unroll
                for (int nf = 0; nf < 8; nf++) {
                    float bx = Ksm[(nf * 8 + g) * 68 + k8 * 8 + tg];
                    float by = Ksm[(nf * 8 + g) * 68 + k8 * 8 + tg + 4];
                    mma16n8k8(sacc[nf], qf[k8], bx, by);
                }
            }

            const int row0 = qb + w * 16 + g;
            const int row1 = row0 + 8;
#pragma unroll
            for (int nf = 0; nf < 8; nf++) {
#pragma unroll
                for (int e = 0; e < 2; e++) {
                    int key = kt + nf * 8 + tg * 2 + e;
                    if (key > row0) sacc[nf][e]     = -1e30f;
                    if (key > row1) sacc[nf][2 + e] = -1e30f;
                }
            }
            float t0 = -1e30f, t1 = -1e30f;
#pragma unroll
            for (int nf = 0; nf < 8; nf++) {
                t0 = fmaxf(t0, fmaxf(sacc[nf][0], sacc[nf][1]));
                t1 = fmaxf(t1, fmaxf(sacc[nf][2], sacc[nf][3]));
            }
            t0 = fmaxf(t0, __shfl_xor_sync(0xFFFFFFFFu, t0, 1));
            t0 = fmaxf(t0, __shfl_xor_sync(0xFFFFFFFFu, t0, 2));
            t1 = fmaxf(t1, __shfl_xor_sync(0xFFFFFFFFu, t1, 1));
            t1 = fmaxf(t1, __shfl_xor_sync(0xFFFFFFFFu, t1, 2));
            float nm0 = fmaxf(m0, t0);
            float nm1 = fmaxf(m1, t1);
            float c0 = __expf(m0 - nm0);
            float c1 = __expf(m1 - nm1);
            m0 = nm0; m1 = nm1;

            float ps0 = 0.0f, ps1 = 0.0f;
#pragma unroll
            for (int nf = 0; nf < 8; nf++) {
#pragma unroll
                for (int e = 0; e < 2; e++) {
                    float p0 = __expf(sacc[nf][e]     - nm0);
                    float p1 = __expf(sacc[nf][2 + e] - nm1);
                    sacc[nf][e]     = p0;
                    sacc[nf][2 + e] = p1;
                    ps0 += p0; ps1 += p1;
                }
            }
            ps0 += __shfl_xor_sync(0xFFFFFFFFu, ps0, 1);
            ps0 += __shfl_xor_sync(0xFFFFFFFFu, ps0, 2);
            ps1 += __shfl_xor_sync(0xFFFFFFFFu, ps1, 1);
            ps1 += __shfl_xor_sync(0xFFFFFFFFu, ps1, 2);
            l0 = l0 * c0 + ps0;
            l1 = l1 * c1 + ps1;

#pragma unroll
            for (int nf2 = 0; nf2 < 8; nf2++) {
                oacc[nf2][0] *= c0; oacc[nf2][1] *= c0;
                oacc[nf2][2] *= c1; oacc[nf2][3] *= c1;
            }

            // PV phase A
#pragma unroll
            for (int nf = 0; nf < 4; nf++) {
                float2 lo = make_float2(tf32r(sacc[nf][0]), tf32r(sacc[nf][1]));
                float2 hi = make_float2(tf32r(sacc[nf][2]), tf32r(sacc[nf][3]));
                *(float2*)&Pw[g * 36 + nf * 8 + tg * 2]       = lo;
                *(float2*)&Pw[(g + 8) * 36 + nf * 8 + tg * 2] = hi;
            }
            __syncwarp();
#pragma unroll
            for (int kk = 0; kk < 4; kk++) {
                float af[4];
                af[0] = Pw[g * 36 + kk * 8 + tg];
                af[1] = Pw[(g + 8) * 36 + kk * 8 + tg];
                af[2] = Pw[g * 36 + kk * 8 + tg + 4];
                af[3] = Pw[(g + 8) * 36 + kk * 8 + tg + 4];
#pragma unroll
                for (int nf2 = 0; nf2 < 8; nf2++) {
                    float bx = Vsm[(kk * 8 + tg) * 72 + nf2 * 8 + g];
                    float by = Vsm[(kk * 8 + tg + 4) * 72 + nf2 * 8 + g];
                    mma16n8k8(oacc[nf2], af, bx, by);
                }
            }
            __syncwarp();

            // PV phase B
#pragma unroll
            for (int nf = 4; nf < 8; nf++) {
                float2 lo = make_float2(tf32r(sacc[nf][0]), tf32r(sacc[nf][1]));
                float2 hi = make_float2(tf32r(sacc[nf][2]), tf32r(sacc[nf][3]));
                *(float2*)&Pw[g * 36 + (nf - 4) * 8 + tg * 2]       = lo;
                *(float2*)&Pw[(g + 8) * 36 + (nf - 4) * 8 + tg * 2] = hi;
            }
            __syncwarp();
#pragma unroll
            for (int kk = 0; kk < 4; kk++) {
                float af[4];
                af[0] = Pw[g * 36 + kk * 8 + tg];
                af[1] = Pw[(g + 8) * 36 + kk * 8 + tg];
                af[2] = Pw[g * 36 + kk * 8 + tg + 4];
                af[3] = Pw[(g + 8) * 36 + kk * 8 + tg + 4];
#pragma unroll
                for (int nf2 = 0; nf2 < 8; nf2++) {
                    float bx = Vsm[(32 + kk * 8 + tg) * 72 + nf2 * 8 + g];
                    float by = Vsm[(32 + kk * 8 + tg + 4) * 72 + nf2 * 8 + g];
                    mma16n8k8(oacc[nf2], af, bx, by);
                }
            }
        }
        __syncthreads();
    }

    // epilogue: normalize + fp16 fragment-major scatter
    {
        const int row0 = b * SS + qb + w * 16 + g;
        const int row1 = row0 + 8;
        const float inv0 = 1.0f / l0;
        const float inv1 = 1.0f / l1;
#pragma unroll
        for (int nf2 = 0; nf2 < 8; nf2++) {
            const int col = h * HD + nf2 * 8 + tg * 2;
            scatterA_pair(afrag, row0, col,
                          __floats2half2_rn(oacc[nf2][0] * inv0, oacc[nf2][1] * inv0));
            scatterA_pair(afrag, row1, col,
                          __floats2half2_rn(oacc[nf2][2] * inv1, oacc[nf2][3] * inv1));
        }
    }
}

// ------- residual add + layernorm; also emits fp16 fragment-major x --------
__global__ void __launch_bounds__(256)
ln_res_kernel(float* __restrict__ x, const float* __restrict__ res,
              const float* __restrict__ g, const float* __restrict__ beta,
              __half* __restrict__ afrag)
{
    __shared__ float red[256];
    const int row = blockIdx.x;
    const int tid = threadIdx.x;
    const int d0  = tid * 4;
    float* xr = x + (size_t)row * DD;
    const float* rr = res + (size_t)row * DD;

    float y[4];
    float s = 0.0f;
    {
        float4 xv = *(const float4*)(xr + d0);
        float4 rv = *(const float4*)(rr + d0);
        y[0] = xv.x + rv.x; y[1] = xv.y + rv.y;
        y[2] = xv.z + rv.z; y[3] = xv.w + rv.w;
        s = y[0] + y[1] + y[2] + y[3];
    }
    red[tid] = s; __syncthreads();
    for (int off = 128; off > 0; off >>= 1) {
        if (tid < off) red[tid] += red[tid + off];
        __syncthreads();
    }
    float mu = red[0] * (1.0f / (float)DD);
    __syncthreads();

    float vs = 0.0f;
#pragma unroll
    for (int i = 0; i < 4; i++) {
        float d2 = y[i] - mu;
        vs += d2 * d2;
    }
    red[tid] = vs; __syncthreads();
    for (int off = 128; off > 0; off >>= 1) {
        if (tid < off) red[tid] += red[tid + off];
        __syncthreads();
    }
    float var = red[0] * (1.0f / (float)DD);
    float inv = rsqrtf(var + 1e-5f);

    float out[4];
#pragma unroll
    for (int i = 0; i < 4; i++)
        out[i] = (y[i] - mu) * inv * g[d0 + i] + beta[d0 + i];
    *(float4*)(xr + d0) = *(float4*)out;
    scatterA_pair(afrag, row, d0,     __floats2half2_rn(out[0], out[1]));
    scatterA_pair(afrag, row, d0 + 2, __floats2half2_rn(out[2], out[3]));
}

// ---------------------------------------------------------------------------
extern "C" void kernel_launch(void* const* d_in, const int* in_sizes, int n_in,
                              void* d_out, int out_size)
{
    const int*   tokens = (const int*)  d_in[0];
    const float* emb    = (const float*)d_in[1];
    const float* qw     = (const float*)d_in[2];
    const float* qb     = (const float*)d_in[3];
    const float* kw     = (const float*)d_in[4];
    const float* kb     = (const float*)d_in[5];
    const float* vw     = (const float*)d_in[6];
    const float* vb     = (const float*)d_in[7];
    const float* ow     = (const float*)d_in[8];
    const float* ob     = (const float*)d_in[9];
    const float* ln_g   = (const float*)d_in[10];
    const float* ln_b   = (const float*)d_in[11];
    const float* out_w  = (const float*)d_in[12];
    const float* out_b  = (const float*)d_in[13];
    float* logits = (float*)d_out;

    float *x, *q, *k, *v, *attn;
    __half *afrag, *wfrag, *lwf;
    cudaGetSymbolAddress((void**)&x,     g_x);
    cudaGetSymbolAddress((void**)&q,     g_q);
    cudaGetSymbolAddress((void**)&k,     g_k);
    cudaGetSymbolAddress((void**)&v,     g_v);
    cudaGetSymbolAddress((void**)&attn,  g_attn);
    cudaGetSymbolAddress((void**)&afrag, g_afrag);
    cudaGetSymbolAddress((void**)&wfrag, g_wfrag);
    cudaGetSymbolAddress((void**)&lwf,   g_lwf);

    cudaFuncSetAttribute(gemm_pre,        cudaFuncAttributeMaxDynamicSharedMemorySize, GEMM_PRE_SMEM_BYTES);
    cudaFuncSetAttribute(gemm_pre_qkv,    cudaFuncAttributeMaxDynamicSharedMemorySize, GEMM_PRE_SMEM_BYTES);
    cudaFuncSetAttribute(attn_mma_kernel, cudaFuncAttributeMaxDynamicSharedMemorySize, ATTN_SMEM_BYTES);

    const size_t WMAT = (size_t)NT_D * KC2 * CHUNK_H;   // halves per layer matrix

    // weight prelayouts: logits (one launch) + ALL 16 layer mats (one launch)
    {
        dim3 gw(KC2, NT_OUT);             // (16, 250)
        prelayout_W<<<gw, 256>>>(out_w, wfrag, VV);
        dim3 gall(KC2, NT_D, LL * 4);     // (16, 8, 16)
        prelayout_W_all<<<gall, 256>>>(qw, kw, vw, ow, lwf);
    }

    embed_kernel<<<NROW, 256>>>(tokens, emb, x, afrag);

    dim3 gqkv(MT_A, NT_D, 3);             // (16, 8, 3)
    dim3 gproj(MT_A, NT_D);               // (16, 8)
    dim3 gattn(SS / 128, HH, BB);         // (8, 16, 2)

    for (int l = 0; l < LL; l++) {
        size_t bo = (size_t)l * DD;
        gemm_pre_qkv<<<gqkv, 256, GEMM_PRE_SMEM_BYTES>>>(
            afrag,
            lwf + (size_t)(l * 4 + 0) * WMAT,
            lwf + (size_t)(l * 4 + 1) * WMAT,
            lwf + (size_t)(l * 4 + 2) * WMAT,
            qb + bo, kb + bo, vb + bo, q, k, v);
        attn_mma_kernel<<<gattn, 256, ATTN_SMEM_BYTES>>>(q, k, v, afrag);
        gemm_pre<<<gproj, 256, GEMM_PRE_SMEM_BYTES>>>(
            afrag, lwf + (size_t)(l * 4 + 3) * WMAT, ob + bo, attn, DD, KC2);
        ln_res_kernel<<<NROW, 256>>>(x, attn, ln_g + bo, ln_b + bo, afrag);
    }

    // final logits
    dim3 gout(MT_A, NT_OUT);              // (16, 250)
    gemm_pre<<<gout, 256, GEMM_PRE_SMEM_BYTES>>>(afrag, wfrag, out_b, logits, VV, KC2);
}